// round 4
// baseline (speedup 1.0000x reference)
#include <cuda_runtime.h>
#include <cstdint>
#include <cstddef>

// Problem constants
#define B_   8
#define S_   1024
#define D_   1024
#define H_   16
#define HD_  64
#define OD_  3072              // 3*D
#define ROWS_ (B_ * S_)        // 8192
#define BHSZ_ (B_ * H_ * S_ * HD_)  // 8,388,608 floats per tensor

#define NEG_BIG (-3.0e38f)

// Scratch (device globals, no allocation)
__device__ float g_lo[ROWS_ * 4];
__device__ float g_Q[BHSZ_];
__device__ float g_K[BHSZ_];
__device__ float g_V[BHSZ_];

// ---------------------------------------------------------------------------
// Kernel 1: lo[b,s,r] = sum_d h[b,s,d] * lora_A[adapter[b], r, d]
// One block per (b,s) row, 128 threads.
// ---------------------------------------------------------------------------
__global__ __launch_bounds__(128) void lo_kernel(const float* __restrict__ Hs,
                                                 const float* __restrict__ lA,
                                                 const int*   __restrict__ am) {
    const int row = blockIdx.x;          // 0..8191
    const int b   = row >> 10;
    const int a   = am[b];
    const float* hr = Hs + (size_t)row * D_;
    const float* A  = lA + (size_t)a * 4 * D_;

    float p0 = 0.f, p1 = 0.f, p2 = 0.f, p3 = 0.f;
    for (int d = threadIdx.x; d < D_; d += 128) {
        float hv = hr[d];
        p0 += hv * A[d];
        p1 += hv * A[D_ + d];
        p2 += hv * A[2 * D_ + d];
        p3 += hv * A[3 * D_ + d];
    }
    __shared__ float red[4][128];
    red[0][threadIdx.x] = p0;
    red[1][threadIdx.x] = p1;
    red[2][threadIdx.x] = p2;
    red[3][threadIdx.x] = p3;
    __syncthreads();
    for (int off = 64; off > 0; off >>= 1) {
        if (threadIdx.x < off) {
            red[0][threadIdx.x] += red[0][threadIdx.x + off];
            red[1][threadIdx.x] += red[1][threadIdx.x + off];
            red[2][threadIdx.x] += red[2][threadIdx.x + off];
            red[3][threadIdx.x] += red[3][threadIdx.x + off];
        }
        __syncthreads();
    }
    if (threadIdx.x < 4)
        g_lo[row * 4 + threadIdx.x] = red[threadIdx.x][0];
}

// ---------------------------------------------------------------------------
// Kernel 2: QKV GEMM (8192 x 3072, K=1024) + bias + LoRA delta + RoPE.
// Block tile 64x64, BK=32, 256 threads, 4x4 micro-tile (rows ty+16i, cols tx+16j).
// Block column spans exactly one (part, head); RoPE pairs (d, d+32) are both
// owned by the same thread (cols tx+16j), so RoPE is applied in-register.
// Writes Q/K/V in [b*H+h][s][d] layout.
// ---------------------------------------------------------------------------
__global__ __launch_bounds__(256) void qkv_kernel(
    const float* __restrict__ Hs, const float* __restrict__ W,
    const float* __restrict__ bias, const float* __restrict__ lB,
    const int* __restrict__ am,
    const float* __restrict__ cosp, const float* __restrict__ sinp) {

    __shared__ float As[64][33];
    __shared__ float Bs[32][65];

    const int rowBase = blockIdx.y * 64;
    const int colBase = blockIdx.x * 64;
    const int t  = threadIdx.x;
    const int tx = t & 15, ty = t >> 4;

    float acc[4][4];
#pragma unroll
    for (int i = 0; i < 4; i++)
#pragma unroll
        for (int j = 0; j < 4; j++) acc[i][j] = 0.f;

    for (int k0 = 0; k0 < D_; k0 += 32) {
#pragma unroll
        for (int l = 0; l < 2; l++) {
            int idx = t + l * 256;
            int r = idx >> 3, c4 = (idx & 7) << 2;
            float4 v = *(const float4*)(Hs + (size_t)(rowBase + r) * D_ + k0 + c4);
            As[r][c4 + 0] = v.x; As[r][c4 + 1] = v.y;
            As[r][c4 + 2] = v.z; As[r][c4 + 3] = v.w;
        }
#pragma unroll
        for (int l = 0; l < 2; l++) {
            int idx = t + l * 256;
            int c = idx >> 3, k4 = (idx & 7) << 2;
            float4 v = *(const float4*)(W + (size_t)(colBase + c) * D_ + k0 + k4);
            Bs[k4 + 0][c] = v.x; Bs[k4 + 1][c] = v.y;
            Bs[k4 + 2][c] = v.z; Bs[k4 + 3][c] = v.w;
        }
        __syncthreads();
#pragma unroll
        for (int k = 0; k < 32; k++) {
            float a0 = As[ty][k], a1 = As[ty + 16][k], a2 = As[ty + 32][k], a3 = As[ty + 48][k];
            float b0 = Bs[k][tx], b1 = Bs[k][tx + 16], b2 = Bs[k][tx + 32], b3 = Bs[k][tx + 48];
            acc[0][0] += a0 * b0; acc[0][1] += a0 * b1; acc[0][2] += a0 * b2; acc[0][3] += a0 * b3;
            acc[1][0] += a1 * b0; acc[1][1] += a1 * b1; acc[1][2] += a1 * b2; acc[1][3] += a1 * b3;
            acc[2][0] += a2 * b0; acc[2][1] += a2 * b1; acc[2][2] += a2 * b2; acc[2][3] += a2 * b3;
            acc[3][0] += a3 * b0; acc[3][1] += a3 * b1; acc[3][2] += a3 * b2; acc[3][3] += a3 * b3;
        }
        __syncthreads();
    }

    // Epilogue: bias + LoRA delta + RoPE, write to Q/K/V scratch.
    const int b    = rowBase >> 10;      // 64-row tiles never straddle batches
    const int a    = am[b];
    const int part = colBase >> 10;      // 0=Q, 1=K, 2=V
    const int h    = (colBase & 1023) >> 6;
    float* dst = (part == 0) ? g_Q : (part == 1) ? g_K : g_V;

    float biasv[4];
    float Bw[4][4];
#pragma unroll
    for (int j = 0; j < 4; j++) {
        int o = colBase + tx + 16 * j;
        biasv[j] = bias[o];
        const float* bw = lB + ((size_t)a * OD_ + o) * 4;
        Bw[j][0] = bw[0]; Bw[j][1] = bw[1]; Bw[j][2] = bw[2]; Bw[j][3] = bw[3];
    }

#pragma unroll
    for (int i = 0; i < 4; i++) {
        int row = rowBase + ty + 16 * i;
        int s   = row & 1023;
        const float* lo = g_lo + row * 4;
        float l0 = lo[0], l1 = lo[1], l2 = lo[2], l3 = lo[3];
        float v[4];
#pragma unroll
        for (int j = 0; j < 4; j++) {
            v[j] = acc[i][j] + biasv[j]
                 + 0.25f * (l0 * Bw[j][0] + l1 * Bw[j][1] + l2 * Bw[j][2] + l3 * Bw[j][3]);
        }
        if (part < 2) {
            // RoPE. d = tx + 16*j; pairs (j, j+2) are (d, d+32).
            const float* cr = cosp + (size_t)row * HD_;
            const float* sr = sinp + (size_t)row * HD_;
#pragma unroll
            for (int j = 0; j < 2; j++) {
                int d1 = tx + 16 * j;
                float c1 = cr[d1], s1 = sr[d1];
                float c2 = cr[d1 + 32], s2 = sr[d1 + 32];
                float vl = v[j], vh = v[j + 2];
                v[j]     = vl * c1 - vh * s1;
                v[j + 2] = vh * c2 + vl * s2;
            }
        }
        float* drow = dst + ((size_t)(b * H_ + h) * S_ + s) * HD_;
#pragma unroll
        for (int j = 0; j < 4; j++) drow[tx + 16 * j] = v[j];
    }
}

// ---------------------------------------------------------------------------
// Kernel 3: flash attention. Block = (b,h) x 64-query tile, 256 threads.
// Per thread: 4x4 micro-tile in both S = Q·Kᵀ and O += P·V GEMMs.
// Online softmax; per-row (m, l) tracked redundantly across the 16-lane tx
// group via shuffle reductions. Ps aliases Ks (K only read in score phase).
// Dynamic smem: Qs[64][65] + Ks/Ps[64][65] + Vs[64][64] + mask[64] = 49920 B.
// ---------------------------------------------------------------------------
__global__ __launch_bounds__(256) void attn_kernel(const float* __restrict__ mask,
                                                   float* __restrict__ out) {
    extern __shared__ float sm[];
    float* Qs    = sm;                       // [64][65]
    float* Ks    = sm + 64 * 65;             // [64][65], aliased as Ps
    float* Vs    = sm + 2 * 64 * 65;         // [64][64]
    float* maskS = sm + 2 * 64 * 65 + 64 * 64;  // [64]

    const int bh = blockIdx.y;               // 0..127
    const int b  = bh >> 4;
    const int h  = bh & 15;
    const int qt = blockIdx.x;               // 0..15
    const int t  = threadIdx.x;
    const int tx = t & 15, ty = t >> 4;

    // Load Q tile (64 x 64)
    const float* Qg = g_Q + (size_t)bh * (S_ * HD_) + qt * 64 * HD_;
#pragma unroll
    for (int l = 0; l < 4; l++) {
        int idx = t + l * 256;
        int r = idx >> 4, c4 = (idx & 15) << 2;
        float4 v = *(const float4*)(Qg + r * HD_ + c4);
        Qs[r * 65 + c4 + 0] = v.x; Qs[r * 65 + c4 + 1] = v.y;
        Qs[r * 65 + c4 + 2] = v.z; Qs[r * 65 + c4 + 3] = v.w;
    }

    float m[4], lsum[4], o[4][4];
#pragma unroll
    for (int i = 0; i < 4; i++) {
        m[i] = NEG_BIG; lsum[i] = 0.f;
#pragma unroll
        for (int j = 0; j < 4; j++) o[i][j] = 0.f;
    }

    const float* maskb = mask + b * S_;

    for (int kt = 0; kt < 16; kt++) {
        __syncthreads();  // prior tile's smem reads complete (incl. first Q load)
        const float* Kg = g_K + (size_t)bh * (S_ * HD_) + kt * 64 * HD_;
        const float* Vg = g_V + (size_t)bh * (S_ * HD_) + kt * 64 * HD_;
#pragma unroll
        for (int l = 0; l < 4; l++) {
            int idx = t + l * 256;
            int r = idx >> 4, c4 = (idx & 15) << 2;
            float4 kv = *(const float4*)(Kg + r * HD_ + c4);
            Ks[r * 65 + c4 + 0] = kv.x; Ks[r * 65 + c4 + 1] = kv.y;
            Ks[r * 65 + c4 + 2] = kv.z; Ks[r * 65 + c4 + 3] = kv.w;
            float4 vv = *(const float4*)(Vg + r * HD_ + c4);
            *(float4*)(Vs + r * 64 + c4) = vv;
        }
        if (t < 64) maskS[t] = maskb[kt * 64 + t];
        __syncthreads();

        // Score GEMM: acc[i][j] = Q[ty+16i] . K[tx+16j]
        float acc[4][4];
#pragma unroll
        for (int i = 0; i < 4; i++)
#pragma unroll
            for (int j = 0; j < 4; j++) acc[i][j] = 0.f;

#pragma unroll 16
        for (int k = 0; k < 64; k++) {
            float q0 = Qs[ty * 65 + k],        q1 = Qs[(ty + 16) * 65 + k];
            float q2 = Qs[(ty + 32) * 65 + k], q3 = Qs[(ty + 48) * 65 + k];
            float k0 = Ks[tx * 65 + k],        k1 = Ks[(tx + 16) * 65 + k];
            float k2 = Ks[(tx + 32) * 65 + k], k3 = Ks[(tx + 48) * 65 + k];
            acc[0][0] += q0 * k0; acc[0][1] += q0 * k1; acc[0][2] += q0 * k2; acc[0][3] += q0 * k3;
            acc[1][0] += q1 * k0; acc[1][1] += q1 * k1; acc[1][2] += q1 * k2; acc[1][3] += q1 * k3;
            acc[2][0] += q2 * k0; acc[2][1] += q2 * k1; acc[2][2] += q2 * k2; acc[2][3] += q2 * k3;
            acc[3][0] += q3 * k0; acc[3][1] += q3 * k1; acc[3][2] += q3 * k2; acc[3][3] += q3 * k3;
        }

        // Scale + mask + per-row tile max (shuffle over 16-lane tx group)
        float mt[4];
#pragma unroll
        for (int i = 0; i < 4; i++) {
            float rm = NEG_BIG;
#pragma unroll
            for (int j = 0; j < 4; j++) {
                acc[i][j] = acc[i][j] * 0.125f + maskS[tx + 16 * j];
                rm = fmaxf(rm, acc[i][j]);
            }
#pragma unroll
            for (int off = 8; off > 0; off >>= 1)
                rm = fmaxf(rm, __shfl_xor_sync(0xffffffffu, rm, off));
            mt[i] = rm;
        }

        __syncthreads();  // all score-phase reads of Ks done before Ps overwrites it

        float alpha[4];
#pragma unroll
        for (int i = 0; i < 4; i++) {
            float mnew = fmaxf(m[i], mt[i]);
            float ls = 0.f;
#pragma unroll
            for (int j = 0; j < 4; j++) {
                float p = __expf(acc[i][j] - mnew);
                Ks[(ty + 16 * i) * 65 + tx + 16 * j] = p;  // Ps
                ls += p;
            }
#pragma unroll
            for (int off = 8; off > 0; off >>= 1)
                ls += __shfl_xor_sync(0xffffffffu, ls, off);
            alpha[i] = __expf(m[i] - mnew);
            m[i]    = mnew;
            lsum[i] = lsum[i] * alpha[i] + ls;
        }
#pragma unroll
        for (int i = 0; i < 4; i++)
#pragma unroll
            for (int j = 0; j < 4; j++) o[i][j] *= alpha[i];

        __syncthreads();  // Ps fully written

        // O += P . V  (rows ty+16i, cols tx+16j)
#pragma unroll 16
        for (int j = 0; j < 64; j++) {
            float p0 = Ks[ty * 65 + j],        p1 = Ks[(ty + 16) * 65 + j];
            float p2 = Ks[(ty + 32) * 65 + j], p3 = Ks[(ty + 48) * 65 + j];
            float v0 = Vs[j * 64 + tx],        v1 = Vs[j * 64 + tx + 16];
            float v2 = Vs[j * 64 + tx + 32],   v3 = Vs[j * 64 + tx + 48];
            o[0][0] += p0 * v0; o[0][1] += p0 * v1; o[0][2] += p0 * v2; o[0][3] += p0 * v3;
            o[1][0] += p1 * v0; o[1][1] += p1 * v1; o[1][2] += p1 * v2; o[1][3] += p1 * v3;
            o[2][0] += p2 * v0; o[2][1] += p2 * v1; o[2][2] += p2 * v2; o[2][3] += p2 * v3;
            o[3][0] += p3 * v0; o[3][1] += p3 * v1; o[3][2] += p3 * v2; o[3][3] += p3 * v3;
        }
    }

    // Normalize and restage through Qs for coalesced output write.
#pragma unroll
    for (int i = 0; i < 4; i++) {
        float inv = 1.f / lsum[i];
#pragma unroll
        for (int j = 0; j < 4; j++)
            Qs[(ty + 16 * i) * 65 + tx + 16 * j] = o[i][j] * inv;
    }
    __syncthreads();

    // out[b, s, h*64 + c], s = qt*64 + r
    float* outb = out + ((size_t)b * S_ + qt * 64) * D_ + h * HD_;
#pragma unroll
    for (int l = 0; l < 16; l++) {
        int idx = t + l * 256;
        int r = idx >> 6, c = idx & 63;
        outb[(size_t)r * D_ + c] = Qs[r * 65 + c];
    }
}

// ---------------------------------------------------------------------------
// Launch
// Inputs (metadata order):
// 0 hidden_states (8,1024,1024) f32   1 attention_mask (8,1,1,1024) f32
// 2 cos (8,1024,64) f32               3 sin (8,1024,64) f32
// 4 adapter_mask (8,) i32             5 Wqkv_weight (3072,1024) f32
// 6 Wqkv_bias (3072,) f32             7 lora_A (5,4,1024) f32
// 8 lora_B (5,3072,4) f32             out (8,1024,1024) f32
// ---------------------------------------------------------------------------
extern "C" void kernel_launch(void* const* d_in, const int* in_sizes, int n_in,
                              void* d_out, int out_size) {
    (void)in_sizes; (void)n_in; (void)out_size;
    const float* Hs   = (const float*)d_in[0];
    const float* mask = (const float*)d_in[1];
    const float* cosp = (const float*)d_in[2];
    const float* sinp = (const float*)d_in[3];
    const int*   am   = (const int*)d_in[4];
    const float* W    = (const float*)d_in[5];
    const float* bias = (const float*)d_in[6];
    const float* lA   = (const float*)d_in[7];
    const float* lB   = (const float*)d_in[8];
    float* out = (float*)d_out;

    const int attn_smem = (2 * 64 * 65 + 64 * 64 + 64) * (int)sizeof(float); // 49920
    cudaFuncSetAttribute(attn_kernel, cudaFuncAttributeMaxDynamicSharedMemorySize, attn_smem);

    lo_kernel<<<ROWS_, 128>>>(Hs, lA, am);
    qkv_kernel<<<dim3(OD_ / 64, ROWS_ / 64), 256>>>(Hs, W, bias, lB, am, cosp, sinp);
    attn_kernel<<<dim3(S_ / 64, B_ * H_), 256, attn_smem>>>(mask, out);
}

// round 10
// speedup vs baseline: 1.6833x; 1.6833x over previous
#include <cuda_runtime.h>
#include <cuda_bf16.h>
#include <cstdint>
#include <cstddef>

// Problem constants
#define B_   8
#define S_   1024
#define D_   1024
#define H_   16
#define HD_  64
#define OD_  3072
#define ROWS_ (B_ * S_)             // 8192
#define BHSZ_ (B_ * H_ * S_ * HD_) // 8,388,608

#define NEG_BIG (-3.0e38f)

// Scratch (device globals, no allocation)
__device__ float g_lo[ROWS_ * 4];
__device__ float g_Q[BHSZ_];
__device__ float g_K[BHSZ_];
__device__ float g_V[BHSZ_];
__device__ __nv_bfloat16 g_Ah[ROWS_ * D_];
__device__ __nv_bfloat16 g_Al[ROWS_ * D_];
__device__ __nv_bfloat16 g_Bh[OD_ * D_];
__device__ __nv_bfloat16 g_Bl[OD_ * D_];

// ---------------------------------------------------------------------------
// Helpers (sm_80-level features only: cp.async, ldmatrix, mma.sync)
// ---------------------------------------------------------------------------
__device__ __forceinline__ uint32_t smem_u32(const void* p) {
    return (uint32_t)__cvta_generic_to_shared(p);
}
__device__ __forceinline__ void cp16(uint32_t dst, const void* src) {
    asm volatile("cp.async.cg.shared.global [%0], [%1], 16;" :: "r"(dst), "l"(src));
}
__device__ __forceinline__ void ldsm4(uint32_t* r, uint32_t addr) {
    asm volatile("ldmatrix.sync.aligned.m8n8.x4.shared.b16 {%0,%1,%2,%3}, [%4];"
                 : "=r"(r[0]), "=r"(r[1]), "=r"(r[2]), "=r"(r[3]) : "r"(addr));
}
__device__ __forceinline__ void mma16816(float* c, const uint32_t* a,
                                         uint32_t b0, uint32_t b1) {
    asm volatile(
        "mma.sync.aligned.m16n8k16.row.col.f32.bf16.bf16.f32 "
        "{%0,%1,%2,%3}, {%4,%5,%6,%7}, {%8,%9}, {%0,%1,%2,%3};"
        : "+f"(c[0]), "+f"(c[1]), "+f"(c[2]), "+f"(c[3])
        : "r"(a[0]), "r"(a[1]), "r"(a[2]), "r"(a[3]), "r"(b0), "r"(b1));
}
__device__ __forceinline__ float dot4(float4 a, float4 b) {
    return a.x * b.x + a.y * b.y + a.z * b.z + a.w * b.w;
}
// Swizzled byte offset of 16B chunk (r, cc) in a 128x32 bf16 tile (64B rows).
// 8 consecutive rows at fixed cc hit 8 distinct 16B slots mod 128B.
__device__ __forceinline__ uint32_t swz(int r, int cc) {
    return (uint32_t)(r * 64 + ((cc ^ ((r >> 1) & 3)) << 4));
}

// ---------------------------------------------------------------------------
// bf16 split kernels: x = hi + lo (each bf16)
// ---------------------------------------------------------------------------
__global__ __launch_bounds__(256) void splitA_kernel(const float* __restrict__ src) {
    int i = blockIdx.x * 256 + threadIdx.x;
    float x = src[i];
    __nv_bfloat16 h = __float2bfloat16_rn(x);
    g_Ah[i] = h;
    g_Al[i] = __float2bfloat16_rn(x - __bfloat162float(h));
}
__global__ __launch_bounds__(256) void splitB_kernel(const float* __restrict__ src) {
    int i = blockIdx.x * 256 + threadIdx.x;
    float x = src[i];
    __nv_bfloat16 h = __float2bfloat16_rn(x);
    g_Bh[i] = h;
    g_Bl[i] = __float2bfloat16_rn(x - __bfloat162float(h));
}

// ---------------------------------------------------------------------------
// Kernel 1: lo[b,s,r] = sum_d h[b,s,d] * lora_A[adapter[b], r, d]
// ---------------------------------------------------------------------------
__global__ __launch_bounds__(128) void lo_kernel(const float* __restrict__ Hs,
                                                 const float* __restrict__ lA,
                                                 const int*   __restrict__ am) {
    const int row = blockIdx.x;
    const int b   = row >> 10;
    const int a   = am[b];
    const float* hr = Hs + (size_t)row * D_;
    const float* A  = lA + (size_t)a * 4 * D_;

    float p0 = 0.f, p1 = 0.f, p2 = 0.f, p3 = 0.f;
    for (int d = threadIdx.x; d < D_; d += 128) {
        float hv = hr[d];
        p0 += hv * A[d];
        p1 += hv * A[D_ + d];
        p2 += hv * A[2 * D_ + d];
        p3 += hv * A[3 * D_ + d];
    }
    __shared__ float red[4][128];
    red[0][threadIdx.x] = p0;
    red[1][threadIdx.x] = p1;
    red[2][threadIdx.x] = p2;
    red[3][threadIdx.x] = p3;
    __syncthreads();
    for (int off = 64; off > 0; off >>= 1) {
        if (threadIdx.x < off) {
            red[0][threadIdx.x] += red[0][threadIdx.x + off];
            red[1][threadIdx.x] += red[1][threadIdx.x + off];
            red[2][threadIdx.x] += red[2][threadIdx.x + off];
            red[3][threadIdx.x] += red[3][threadIdx.x + off];
        }
        __syncthreads();
    }
    if (threadIdx.x < 4)
        g_lo[row * 4 + threadIdx.x] = red[threadIdx.x][0];
}

// ---------------------------------------------------------------------------
// Kernel 2: QKV GEMM via warp-level mma.sync (bf16 split: ah*bh+al*bh+ah*bl).
// CTA 128x128, BK=32, 256 threads = 8 warps (4M x 2N), warp tile 32x64.
// Each warp's 64 N-cols = one head -> RoPE in-register (frag nj <-> nj+4).
// cp.async double-buffered smem, XOR-swizzled for conflict-free ldmatrix.
// ---------------------------------------------------------------------------
#define TILEB 8192
#define BUFB  (4 * TILEB)    // Ah, Al, Bh, Bl tiles
#define QKV_SMEM (2 * BUFB)  // 65536

__global__ __launch_bounds__(256) void qkv_mma_kernel(
    const float* __restrict__ bias, const float* __restrict__ lB,
    const int* __restrict__ am,
    const float* __restrict__ cosp, const float* __restrict__ sinp) {

    extern __shared__ __align__(1024) char dyn[];
    const uint32_t sbase = smem_u32(dyn);

    __shared__ float  s_bias[128];
    __shared__ float4 s_lB[128];

    const int t    = threadIdx.x;
    const int lane = t & 31, wid = t >> 5;
    const int wM = wid >> 1, wN = wid & 1;
    const int rowBase = blockIdx.y * 128;
    const int colBase = blockIdx.x * 128;

    const __nv_bfloat16* gAh = g_Ah + (size_t)rowBase * D_;
    const __nv_bfloat16* gAl = g_Al + (size_t)rowBase * D_;
    const __nv_bfloat16* gBh = g_Bh + (size_t)colBase * D_;
    const __nv_bfloat16* gBl = g_Bl + (size_t)colBase * D_;

    // chunk loader: tile buffer bi, K-chunk kk (32 bf16 wide)
    auto load_chunk = [&](int kk, int bi) {
        uint32_t base = sbase + bi * BUFB;
        int gcolb = kk * 32;
#pragma unroll
        for (int rep = 0; rep < 2; rep++) {
            int idx = rep * 256 + t;
            int r = idx >> 2, cc = idx & 3;
            uint32_t off = swz(r, cc);
            size_t go = (size_t)r * D_ + gcolb + cc * 8;
            cp16(base + off,             gAh + go);
            cp16(base + TILEB + off,     gAl + go);
            cp16(base + 2 * TILEB + off, gBh + go);
            cp16(base + 3 * TILEB + off, gBl + go);
        }
        asm volatile("cp.async.commit_group;");
    };

    float acc[2][8][4];
#pragma unroll
    for (int mi = 0; mi < 2; mi++)
#pragma unroll
        for (int nj = 0; nj < 8; nj++)
#pragma unroll
            for (int e = 0; e < 4; e++) acc[mi][nj][e] = 0.f;

    load_chunk(0, 0);

    for (int kk = 0; kk < 32; kk++) {
        if (kk < 31) {
            load_chunk(kk + 1, (kk + 1) & 1);
            asm volatile("cp.async.wait_group 1;" ::: "memory");
        } else {
            asm volatile("cp.async.wait_group 0;" ::: "memory");
        }
        __syncthreads();

        const uint32_t base = sbase + (kk & 1) * BUFB;
#pragma unroll
        for (int ks = 0; ks < 2; ks++) {
            uint32_t ah[2][4], al[2][4];
            const int arow = wM * 32 + (lane & 15);
            const int acc_c = ks * 2 + (lane >> 4);
#pragma unroll
            for (int mi = 0; mi < 2; mi++) {
                uint32_t off = swz(arow + mi * 16, acc_c);
                ldsm4(ah[mi], base + off);
                ldsm4(al[mi], base + TILEB + off);
            }
            const int nrow0 = wN * 64 + ((lane >> 4) << 3) + (lane & 7);
            const int bcc   = ks * 2 + ((lane >> 3) & 1);
#pragma unroll
            for (int p = 0; p < 4; p++) {
                uint32_t off = swz(nrow0 + p * 16, bcc);
                uint32_t bh4[4], bl4[4];
                ldsm4(bh4, base + 2 * TILEB + off);
                ldsm4(bl4, base + 3 * TILEB + off);
#pragma unroll
                for (int sub = 0; sub < 2; sub++) {
                    const int nj = 2 * p + sub;
#pragma unroll
                    for (int mi = 0; mi < 2; mi++) {
                        mma16816(acc[mi][nj], ah[mi], bh4[2 * sub], bh4[2 * sub + 1]);
                        mma16816(acc[mi][nj], al[mi], bh4[2 * sub], bh4[2 * sub + 1]);
                        mma16816(acc[mi][nj], ah[mi], bl4[2 * sub], bl4[2 * sub + 1]);
                    }
                }
            }
        }
        __syncthreads();
    }

    // ---------------- Epilogue: bias + LoRA + RoPE, write Q/K/V ----------------
    const int b    = rowBase >> 10;
    const int a    = am[b];
    const int part = colBase >> 10;                  // 0=Q, 1=K, 2=V
    const int h    = ((colBase + wN * 64) & 1023) >> 6;
    float* dst = (part == 0) ? g_Q : (part == 1) ? g_K : g_V;

    if (t < 128) {
        int o = colBase + t;
        s_bias[t] = bias[o];
        s_lB[t]   = *(const float4*)(lB + ((size_t)a * OD_ + o) * 4);
    }
    __syncthreads();

    const int g   = lane >> 2;
    const int tig = lane & 3;

#pragma unroll
    for (int mi = 0; mi < 2; mi++) {
#pragma unroll
        for (int hh = 0; hh < 2; hh++) {
            const int row = rowBase + wM * 32 + mi * 16 + hh * 8 + g;
            const int s   = row & 1023;
            const float4 lov = *(const float4*)(g_lo + row * 4);
            float* drow = dst + ((size_t)(b * H_ + h) * S_ + s) * HD_;

            if (part < 2) {
                const float* cr = cosp + (size_t)row * HD_;
                const float* sr = sinp + (size_t)row * HD_;
#pragma unroll
                for (int nj = 0; nj < 4; nj++) {
                    const int c  = nj * 8 + tig * 2;    // even col in head, < 32
                    const int cl = wN * 64 + c;         // col in CTA tile
                    float v0 = acc[mi][nj][hh * 2 + 0]     + s_bias[cl]      + 0.25f * dot4(lov, s_lB[cl]);
                    float v1 = acc[mi][nj][hh * 2 + 1]     + s_bias[cl + 1]  + 0.25f * dot4(lov, s_lB[cl + 1]);
                    float u0 = acc[mi][nj + 4][hh * 2 + 0] + s_bias[cl + 32] + 0.25f * dot4(lov, s_lB[cl + 32]);
                    float u1 = acc[mi][nj + 4][hh * 2 + 1] + s_bias[cl + 33] + 0.25f * dot4(lov, s_lB[cl + 33]);
                    float2 clo = *(const float2*)(cr + c),      slo = *(const float2*)(sr + c);
                    float2 chi = *(const float2*)(cr + c + 32), shi = *(const float2*)(sr + c + 32);
                    float2 olo = make_float2(v0 * clo.x - u0 * slo.x, v1 * clo.y - u1 * slo.y);
                    float2 ohi = make_float2(u0 * chi.x + v0 * shi.x, u1 * chi.y + v1 * shi.y);
                    *(float2*)(drow + c)      = olo;
                    *(float2*)(drow + c + 32) = ohi;
                }
            } else {
#pragma unroll
                for (int nj = 0; nj < 8; nj++) {
                    const int c  = nj * 8 + tig * 2;
                    const int cl = wN * 64 + c;
                    float v0 = acc[mi][nj][hh * 2 + 0] + s_bias[cl]     + 0.25f * dot4(lov, s_lB[cl]);
                    float v1 = acc[mi][nj][hh * 2 + 1] + s_bias[cl + 1] + 0.25f * dot4(lov, s_lB[cl + 1]);
                    *(float2*)(drow + c) = make_float2(v0, v1);
                }
            }
        }
    }
}

// ---------------------------------------------------------------------------
// Kernel 3: flash attention (fp32 SIMT, proven in R4).
// ---------------------------------------------------------------------------
__global__ __launch_bounds__(256) void attn_kernel(const float* __restrict__ mask,
                                                   float* __restrict__ out) {
    extern __shared__ float sm[];
    float* Qs    = sm;                       // [64][65]
    float* Ks    = sm + 64 * 65;             // [64][65], aliased as Ps
    float* Vs    = sm + 2 * 64 * 65;         // [64][64]
    float* maskS = sm + 2 * 64 * 65 + 64 * 64;  // [64]

    const int bh = blockIdx.y;
    const int b  = bh >> 4;
    const int qt = blockIdx.x;
    const int t  = threadIdx.x;
    const int tx = t & 15, ty = t >> 4;

    const float* Qg = g_Q + (size_t)bh * (S_ * HD_) + qt * 64 * HD_;
#pragma unroll
    for (int l = 0; l < 4; l++) {
        int idx = t + l * 256;
        int r = idx >> 4, c4 = (idx & 15) << 2;
        float4 v = *(const float4*)(Qg + r * HD_ + c4);
        Qs[r * 65 + c4 + 0] = v.x; Qs[r * 65 + c4 + 1] = v.y;
        Qs[r * 65 + c4 + 2] = v.z; Qs[r * 65 + c4 + 3] = v.w;
    }

    float m[4], lsum[4], o[4][4];
#pragma unroll
    for (int i = 0; i < 4; i++) {
        m[i] = NEG_BIG; lsum[i] = 0.f;
#pragma unroll
        for (int j = 0; j < 4; j++) o[i][j] = 0.f;
    }

    const float* maskb = mask + b * S_;

    for (int kt = 0; kt < 16; kt++) {
        __syncthreads();
        const float* Kg = g_K + (size_t)bh * (S_ * HD_) + kt * 64 * HD_;
        const float* Vg = g_V + (size_t)bh * (S_ * HD_) + kt * 64 * HD_;
#pragma unroll
        for (int l = 0; l < 4; l++) {
            int idx = t + l * 256;
            int r = idx >> 4, c4 = (idx & 15) << 2;
            float4 kv = *(const float4*)(Kg + r * HD_ + c4);
            Ks[r * 65 + c4 + 0] = kv.x; Ks[r * 65 + c4 + 1] = kv.y;
            Ks[r * 65 + c4 + 2] = kv.z; Ks[r * 65 + c4 + 3] = kv.w;
            float4 vv = *(const float4*)(Vg + r * HD_ + c4);
            *(float4*)(Vs + r * 64 + c4) = vv;
        }
        if (t < 64) maskS[t] = maskb[kt * 64 + t];
        __syncthreads();

        float acc[4][4];
#pragma unroll
        for (int i = 0; i < 4; i++)
#pragma unroll
            for (int j = 0; j < 4; j++) acc[i][j] = 0.f;

#pragma unroll 16
        for (int k = 0; k < 64; k++) {
            float q0 = Qs[ty * 65 + k],        q1 = Qs[(ty + 16) * 65 + k];
            float q2 = Qs[(ty + 32) * 65 + k], q3 = Qs[(ty + 48) * 65 + k];
            float k0 = Ks[tx * 65 + k],        k1 = Ks[(tx + 16) * 65 + k];
            float k2 = Ks[(tx + 32) * 65 + k], k3 = Ks[(tx + 48) * 65 + k];
            acc[0][0] += q0 * k0; acc[0][1] += q0 * k1; acc[0][2] += q0 * k2; acc[0][3] += q0 * k3;
            acc[1][0] += q1 * k0; acc[1][1] += q1 * k1; acc[1][2] += q1 * k2; acc[1][3] += q1 * k3;
            acc[2][0] += q2 * k0; acc[2][1] += q2 * k1; acc[2][2] += q2 * k2; acc[2][3] += q2 * k3;
            acc[3][0] += q3 * k0; acc[3][1] += q3 * k1; acc[3][2] += q3 * k2; acc[3][3] += q3 * k3;
        }

        float mt[4];
#pragma unroll
        for (int i = 0; i < 4; i++) {
            float rm = NEG_BIG;
#pragma unroll
            for (int j = 0; j < 4; j++) {
                acc[i][j] = acc[i][j] * 0.125f + maskS[tx + 16 * j];
                rm = fmaxf(rm, acc[i][j]);
            }
#pragma unroll
            for (int off = 8; off > 0; off >>= 1)
                rm = fmaxf(rm, __shfl_xor_sync(0xffffffffu, rm, off));
            mt[i] = rm;
        }

        __syncthreads();

        float alpha[4];
#pragma unroll
        for (int i = 0; i < 4; i++) {
            float mnew = fmaxf(m[i], mt[i]);
            float ls = 0.f;
#pragma unroll
            for (int j = 0; j < 4; j++) {
                float p = __expf(acc[i][j] - mnew);
                Ks[(ty + 16 * i) * 65 + tx + 16 * j] = p;
                ls += p;
            }
#pragma unroll
            for (int off = 8; off > 0; off >>= 1)
                ls += __shfl_xor_sync(0xffffffffu, ls, off);
            alpha[i] = __expf(m[i] - mnew);
            m[i]    = mnew;
            lsum[i] = lsum[i] * alpha[i] + ls;
        }
#pragma unroll
        for (int i = 0; i < 4; i++)
#pragma unroll
            for (int j = 0; j < 4; j++) o[i][j] *= alpha[i];

        __syncthreads();

#pragma unroll 16
        for (int j = 0; j < 64; j++) {
            float p0 = Ks[ty * 65 + j],        p1 = Ks[(ty + 16) * 65 + j];
            float p2 = Ks[(ty + 32) * 65 + j], p3 = Ks[(ty + 48) * 65 + j];
            float v0 = Vs[j * 64 + tx],        v1 = Vs[j * 64 + tx + 16];
            float v2 = Vs[j * 64 + tx + 32],   v3 = Vs[j * 64 + tx + 48];
            o[0][0] += p0 * v0; o[0][1] += p0 * v1; o[0][2] += p0 * v2; o[0][3] += p0 * v3;
            o[1][0] += p1 * v0; o[1][1] += p1 * v1; o[1][2] += p1 * v2; o[1][3] += p1 * v3;
            o[2][0] += p2 * v0; o[2][1] += p2 * v1; o[2][2] += p2 * v2; o[2][3] += p2 * v3;
            o[3][0] += p3 * v0; o[3][1] += p3 * v1; o[3][2] += p3 * v2; o[3][3] += p3 * v3;
        }
    }

#pragma unroll
    for (int i = 0; i < 4; i++) {
        float inv = 1.f / lsum[i];
#pragma unroll
        for (int j = 0; j < 4; j++)
            Qs[(ty + 16 * i) * 65 + tx + 16 * j] = o[i][j] * inv;
    }
    __syncthreads();

    float* outb = out + ((size_t)b * S_ + qt * 64) * D_ + (blockIdx.y & 15) * HD_;
#pragma unroll
    for (int l = 0; l < 16; l++) {
        int idx = t + l * 256;
        int r = idx >> 6, c = idx & 63;
        outb[(size_t)r * D_ + c] = Qs[r * 65 + c];
    }
}

// ---------------------------------------------------------------------------
// Launch
// ---------------------------------------------------------------------------
extern "C" void kernel_launch(void* const* d_in, const int* in_sizes, int n_in,
                              void* d_out, int out_size) {
    (void)in_sizes; (void)n_in; (void)out_size;
    const float* Hs   = (const float*)d_in[0];
    const float* mask = (const float*)d_in[1];
    const float* cosp = (const float*)d_in[2];
    const float* sinp = (const float*)d_in[3];
    const int*   am   = (const int*)d_in[4];
    const float* W    = (const float*)d_in[5];
    const float* bias = (const float*)d_in[6];
    const float* lA   = (const float*)d_in[7];
    const float* lB   = (const float*)d_in[8];
    float* out = (float*)d_out;

    const int attn_smem = (2 * 64 * 65 + 64 * 64 + 64) * (int)sizeof(float); // 49920
    cudaFuncSetAttribute(attn_kernel, cudaFuncAttributeMaxDynamicSharedMemorySize, attn_smem);
    cudaFuncSetAttribute(qkv_mma_kernel, cudaFuncAttributeMaxDynamicSharedMemorySize, QKV_SMEM);

    splitA_kernel<<<(ROWS_ * D_) / 256, 256>>>(Hs);
    splitB_kernel<<<(OD_ * D_) / 256, 256>>>(W);
    lo_kernel<<<ROWS_, 128>>>(Hs, lA, am);
    qkv_mma_kernel<<<dim3(OD_ / 128, ROWS_ / 128), 256, QKV_SMEM>>>(bias, lB, am, cosp, sinp);
    attn_kernel<<<dim3(S_ / 64, B_ * H_), 256, attn_smem>>>(mask, out);
}

// round 11
// speedup vs baseline: 3.3597x; 1.9959x over previous
#include <cuda_runtime.h>
#include <cuda_bf16.h>
#include <cstdint>
#include <cstddef>

// Problem constants
#define B_   8
#define S_   1024
#define D_   1024
#define H_   16
#define HD_  64
#define OD_  3072
#define ROWS_ (B_ * S_)             // 8192
#define BHSZ_ (B_ * H_ * S_ * HD_) // 8,388,608

#define NEG_BIG (-3.0e38f)

// Scratch (device globals, no allocation)
__device__ float g_lo[ROWS_ * 4];
__device__ __nv_bfloat16 g_Ah[ROWS_ * D_];
__device__ __nv_bfloat16 g_Al[ROWS_ * D_];
__device__ __nv_bfloat16 g_Bh[OD_ * D_];
__device__ __nv_bfloat16 g_Bl[OD_ * D_];
// Q/K/V in bf16 split (hi,lo) pairs, layout [b*H+h][s][d]
__device__ __nv_bfloat16 g_Qh[BHSZ_], g_Ql[BHSZ_];
__device__ __nv_bfloat16 g_Kh[BHSZ_], g_Kl[BHSZ_];
__device__ __nv_bfloat16 g_Vh[BHSZ_], g_Vl[BHSZ_];

// ---------------------------------------------------------------------------
// Helpers (sm_80-level features only: cp.async, ldmatrix, mma.sync)
// ---------------------------------------------------------------------------
__device__ __forceinline__ uint32_t smem_u32(const void* p) {
    return (uint32_t)__cvta_generic_to_shared(p);
}
__device__ __forceinline__ void cp16(uint32_t dst, const void* src) {
    asm volatile("cp.async.cg.shared.global [%0], [%1], 16;" :: "r"(dst), "l"(src));
}
__device__ __forceinline__ void ldsm4(uint32_t* r, uint32_t addr) {
    asm volatile("ldmatrix.sync.aligned.m8n8.x4.shared.b16 {%0,%1,%2,%3}, [%4];"
                 : "=r"(r[0]), "=r"(r[1]), "=r"(r[2]), "=r"(r[3]) : "r"(addr));
}
__device__ __forceinline__ void ldsm4t(uint32_t* r, uint32_t addr) {
    asm volatile("ldmatrix.sync.aligned.m8n8.x4.trans.shared.b16 {%0,%1,%2,%3}, [%4];"
                 : "=r"(r[0]), "=r"(r[1]), "=r"(r[2]), "=r"(r[3]) : "r"(addr));
}
__device__ __forceinline__ void mma16816(float* c, const uint32_t* a,
                                         uint32_t b0, uint32_t b1) {
    asm volatile(
        "mma.sync.aligned.m16n8k16.row.col.f32.bf16.bf16.f32 "
        "{%0,%1,%2,%3}, {%4,%5,%6,%7}, {%8,%9}, {%0,%1,%2,%3};"
        : "+f"(c[0]), "+f"(c[1]), "+f"(c[2]), "+f"(c[3])
        : "r"(a[0]), "r"(a[1]), "r"(a[2]), "r"(a[3]), "r"(b0), "r"(b1));
}
__device__ __forceinline__ float dot4(float4 a, float4 b) {
    return a.x * b.x + a.y * b.y + a.z * b.z + a.w * b.w;
}
// Swizzled byte offset of 16B chunk (r, cc) in a tile with 64B rows (qkv GEMM).
__device__ __forceinline__ uint32_t swz(int r, int cc) {
    return (uint32_t)(r * 64 + ((cc ^ ((r >> 1) & 3)) << 4));
}
// Swizzled byte offset of 16B chunk (r, c in [0,8)) in a tile with 128B rows.
__device__ __forceinline__ uint32_t off128(int r, int c) {
    return (uint32_t)(r * 128 + (((c ^ r) & 7) << 4));
}
// Store fp32 pair as bf16 (hi,lo) split pairs.
__device__ __forceinline__ void store_hl(__nv_bfloat16* dh, __nv_bfloat16* dl,
                                         size_t off, float2 v) {
    __nv_bfloat162 h, l;
    h.x = __float2bfloat16_rn(v.x); h.y = __float2bfloat16_rn(v.y);
    l.x = __float2bfloat16_rn(v.x - __bfloat162float(h.x));
    l.y = __float2bfloat16_rn(v.y - __bfloat162float(h.y));
    *(__nv_bfloat162*)(dh + off) = h;
    *(__nv_bfloat162*)(dl + off) = l;
}

// ---------------------------------------------------------------------------
// bf16 split kernels: x = hi + lo (each bf16)
// ---------------------------------------------------------------------------
__global__ __launch_bounds__(256) void splitA_kernel(const float* __restrict__ src) {
    int i = blockIdx.x * 256 + threadIdx.x;
    float x = src[i];
    __nv_bfloat16 h = __float2bfloat16_rn(x);
    g_Ah[i] = h;
    g_Al[i] = __float2bfloat16_rn(x - __bfloat162float(h));
}
__global__ __launch_bounds__(256) void splitB_kernel(const float* __restrict__ src) {
    int i = blockIdx.x * 256 + threadIdx.x;
    float x = src[i];
    __nv_bfloat16 h = __float2bfloat16_rn(x);
    g_Bh[i] = h;
    g_Bl[i] = __float2bfloat16_rn(x - __bfloat162float(h));
}

// ---------------------------------------------------------------------------
// Kernel 1: lo[b,s,r] = sum_d h[b,s,d] * lora_A[adapter[b], r, d]
// ---------------------------------------------------------------------------
__global__ __launch_bounds__(128) void lo_kernel(const float* __restrict__ Hs,
                                                 const float* __restrict__ lA,
                                                 const int*   __restrict__ am) {
    const int row = blockIdx.x;
    const int b   = row >> 10;
    const int a   = am[b];
    const float* hr = Hs + (size_t)row * D_;
    const float* A  = lA + (size_t)a * 4 * D_;

    float p0 = 0.f, p1 = 0.f, p2 = 0.f, p3 = 0.f;
    for (int d = threadIdx.x; d < D_; d += 128) {
        float hv = hr[d];
        p0 += hv * A[d];
        p1 += hv * A[D_ + d];
        p2 += hv * A[2 * D_ + d];
        p3 += hv * A[3 * D_ + d];
    }
    __shared__ float red[4][128];
    red[0][threadIdx.x] = p0;
    red[1][threadIdx.x] = p1;
    red[2][threadIdx.x] = p2;
    red[3][threadIdx.x] = p3;
    __syncthreads();
    for (int off = 64; off > 0; off >>= 1) {
        if (threadIdx.x < off) {
            red[0][threadIdx.x] += red[0][threadIdx.x + off];
            red[1][threadIdx.x] += red[1][threadIdx.x + off];
            red[2][threadIdx.x] += red[2][threadIdx.x + off];
            red[3][threadIdx.x] += red[3][threadIdx.x + off];
        }
        __syncthreads();
    }
    if (threadIdx.x < 4)
        g_lo[row * 4 + threadIdx.x] = red[threadIdx.x][0];
}

// ---------------------------------------------------------------------------
// Kernel 2: QKV GEMM via warp-level mma.sync (bf16 split: ah*bh+al*bh+ah*bl).
// CTA 128x128, BK=32, 256 threads = 8 warps (4M x 2N), warp tile 32x64.
// Epilogue: bias + LoRA + RoPE, writes Q/K/V as bf16 (hi,lo) split pairs.
// ---------------------------------------------------------------------------
#define TILEB 8192
#define BUFB  (4 * TILEB)
#define QKV_SMEM (2 * BUFB)  // 65536

__global__ __launch_bounds__(256) void qkv_mma_kernel(
    const float* __restrict__ bias, const float* __restrict__ lB,
    const int* __restrict__ am,
    const float* __restrict__ cosp, const float* __restrict__ sinp) {

    extern __shared__ __align__(1024) char dyn[];
    const uint32_t sbase = smem_u32(dyn);

    __shared__ float  s_bias[128];
    __shared__ float4 s_lB[128];

    const int t    = threadIdx.x;
    const int lane = t & 31, wid = t >> 5;
    const int wM = wid >> 1, wN = wid & 1;
    const int rowBase = blockIdx.y * 128;
    const int colBase = blockIdx.x * 128;

    const __nv_bfloat16* gAh = g_Ah + (size_t)rowBase * D_;
    const __nv_bfloat16* gAl = g_Al + (size_t)rowBase * D_;
    const __nv_bfloat16* gBh = g_Bh + (size_t)colBase * D_;
    const __nv_bfloat16* gBl = g_Bl + (size_t)colBase * D_;

    auto load_chunk = [&](int kk, int bi) {
        uint32_t base = sbase + bi * BUFB;
        int gcolb = kk * 32;
#pragma unroll
        for (int rep = 0; rep < 2; rep++) {
            int idx = rep * 256 + t;
            int r = idx >> 2, cc = idx & 3;
            uint32_t off = swz(r, cc);
            size_t go = (size_t)r * D_ + gcolb + cc * 8;
            cp16(base + off,             gAh + go);
            cp16(base + TILEB + off,     gAl + go);
            cp16(base + 2 * TILEB + off, gBh + go);
            cp16(base + 3 * TILEB + off, gBl + go);
        }
        asm volatile("cp.async.commit_group;");
    };

    float acc[2][8][4];
#pragma unroll
    for (int mi = 0; mi < 2; mi++)
#pragma unroll
        for (int nj = 0; nj < 8; nj++)
#pragma unroll
            for (int e = 0; e < 4; e++) acc[mi][nj][e] = 0.f;

    load_chunk(0, 0);

    for (int kk = 0; kk < 32; kk++) {
        if (kk < 31) {
            load_chunk(kk + 1, (kk + 1) & 1);
            asm volatile("cp.async.wait_group 1;" ::: "memory");
        } else {
            asm volatile("cp.async.wait_group 0;" ::: "memory");
        }
        __syncthreads();

        const uint32_t base = sbase + (kk & 1) * BUFB;
#pragma unroll
        for (int ks = 0; ks < 2; ks++) {
            uint32_t ah[2][4], al[2][4];
            const int arow = wM * 32 + (lane & 15);
            const int acc_c = ks * 2 + (lane >> 4);
#pragma unroll
            for (int mi = 0; mi < 2; mi++) {
                uint32_t off = swz(arow + mi * 16, acc_c);
                ldsm4(ah[mi], base + off);
                ldsm4(al[mi], base + TILEB + off);
            }
            const int nrow0 = wN * 64 + ((lane >> 4) << 3) + (lane & 7);
            const int bcc   = ks * 2 + ((lane >> 3) & 1);
#pragma unroll
            for (int p = 0; p < 4; p++) {
                uint32_t off = swz(nrow0 + p * 16, bcc);
                uint32_t bh4[4], bl4[4];
                ldsm4(bh4, base + 2 * TILEB + off);
                ldsm4(bl4, base + 3 * TILEB + off);
#pragma unroll
                for (int sub = 0; sub < 2; sub++) {
                    const int nj = 2 * p + sub;
#pragma unroll
                    for (int mi = 0; mi < 2; mi++) {
                        mma16816(acc[mi][nj], ah[mi], bh4[2 * sub], bh4[2 * sub + 1]);
                        mma16816(acc[mi][nj], al[mi], bh4[2 * sub], bh4[2 * sub + 1]);
                        mma16816(acc[mi][nj], ah[mi], bl4[2 * sub], bl4[2 * sub + 1]);
                    }
                }
            }
        }
        __syncthreads();
    }

    // ---------------- Epilogue ----------------
    const int b    = rowBase >> 10;
    const int a    = am[b];
    const int part = colBase >> 10;                  // 0=Q, 1=K, 2=V
    const int h    = ((colBase + wN * 64) & 1023) >> 6;

    __nv_bfloat16* dh = (part == 0) ? g_Qh : (part == 1) ? g_Kh : g_Vh;
    __nv_bfloat16* dl = (part == 0) ? g_Ql : (part == 1) ? g_Kl : g_Vl;

    if (t < 128) {
        int o = colBase + t;
        s_bias[t] = bias[o];
        s_lB[t]   = *(const float4*)(lB + ((size_t)a * OD_ + o) * 4);
    }
    __syncthreads();

    const int g   = lane >> 2;
    const int tig = lane & 3;

#pragma unroll
    for (int mi = 0; mi < 2; mi++) {
#pragma unroll
        for (int hh = 0; hh < 2; hh++) {
            const int row = rowBase + wM * 32 + mi * 16 + hh * 8 + g;
            const int s   = row & 1023;
            const float4 lov = *(const float4*)(g_lo + row * 4);
            const size_t rowoff = ((size_t)(b * H_ + h) * S_ + s) * HD_;

            if (part < 2) {
                const float* cr = cosp + (size_t)row * HD_;
                const float* sr = sinp + (size_t)row * HD_;
#pragma unroll
                for (int nj = 0; nj < 4; nj++) {
                    const int c  = nj * 8 + tig * 2;
                    const int cl = wN * 64 + c;
                    float v0 = acc[mi][nj][hh * 2 + 0]     + s_bias[cl]      + 0.25f * dot4(lov, s_lB[cl]);
                    float v1 = acc[mi][nj][hh * 2 + 1]     + s_bias[cl + 1]  + 0.25f * dot4(lov, s_lB[cl + 1]);
                    float u0 = acc[mi][nj + 4][hh * 2 + 0] + s_bias[cl + 32] + 0.25f * dot4(lov, s_lB[cl + 32]);
                    float u1 = acc[mi][nj + 4][hh * 2 + 1] + s_bias[cl + 33] + 0.25f * dot4(lov, s_lB[cl + 33]);
                    float2 clo = *(const float2*)(cr + c),      slo = *(const float2*)(sr + c);
                    float2 chi = *(const float2*)(cr + c + 32), shi = *(const float2*)(sr + c + 32);
                    store_hl(dh, dl, rowoff + c,
                             make_float2(v0 * clo.x - u0 * slo.x, v1 * clo.y - u1 * slo.y));
                    store_hl(dh, dl, rowoff + c + 32,
                             make_float2(u0 * chi.x + v0 * shi.x, u1 * chi.y + v1 * shi.y));
                }
            } else {
#pragma unroll
                for (int nj = 0; nj < 8; nj++) {
                    const int c  = nj * 8 + tig * 2;
                    const int cl = wN * 64 + c;
                    float v0 = acc[mi][nj][hh * 2 + 0] + s_bias[cl]     + 0.25f * dot4(lov, s_lB[cl]);
                    float v1 = acc[mi][nj][hh * 2 + 1] + s_bias[cl + 1] + 0.25f * dot4(lov, s_lB[cl + 1]);
                    store_hl(dh, dl, rowoff + c, make_float2(v0, v1));
                }
            }
        }
    }
}

// ---------------------------------------------------------------------------
// Kernel 3: flash attention via mma.sync (bf16 splits everywhere).
// CTA = 64 queries x (b,h); 128 threads = 4 warps x 16 query rows.
// Scores: qh*kh + ql*kh + qh*kl. PV: ph*vh + pl*vh + ph*vl (P split from fp32).
// S C-fragment layout == PV A-fragment layout -> in-register repack.
// smem: Q(h,l) 16KB + 2 x [Kh|Kl|Vh|Vl|mask] 33024B = 82432B -> 2 CTA/SM.
// ---------------------------------------------------------------------------
#define ATT_BUF0 16384
#define ATT_BSTR 33024
#define ATT_SMEM (ATT_BUF0 + 2 * ATT_BSTR)  // 82432

__global__ __launch_bounds__(128) void attn_mma_kernel(const float* __restrict__ mask,
                                                       float* __restrict__ out) {
    extern __shared__ __align__(1024) char adyn[];
    const uint32_t sb = smem_u32(adyn);
    const int t = threadIdx.x, lane = t & 31, w = t >> 5;
    const int g = lane >> 2, tig = lane & 3;
    const int bh = blockIdx.y, b = bh >> 4, h = bh & 15;
    const int qt = blockIdx.x;
    const int qbase = w * 16;

    const __nv_bfloat16* gQh = g_Qh + (size_t)bh * S_ * HD_;
    const __nv_bfloat16* gQl = g_Ql + (size_t)bh * S_ * HD_;
    const __nv_bfloat16* gKh = g_Kh + (size_t)bh * S_ * HD_;
    const __nv_bfloat16* gKl = g_Kl + (size_t)bh * S_ * HD_;
    const __nv_bfloat16* gVh = g_Vh + (size_t)bh * S_ * HD_;
    const __nv_bfloat16* gVl = g_Vl + (size_t)bh * S_ * HD_;
    const float* maskb = mask + b * S_;

    auto load_tile = [&](int kt2, int bi) {
        uint32_t base = sb + ATT_BUF0 + bi * ATT_BSTR;
#pragma unroll
        for (int i = 0; i < 4; i++) {
            int idx = i * 128 + t;
            int r = idx >> 3, c = idx & 7;
            uint32_t off = off128(r, c);
            size_t so = (size_t)(kt2 * 64 + r) * HD_ + c * 8;
            cp16(base + off,         gKh + so);
            cp16(base + 8192 + off,  gKl + so);
            cp16(base + 16384 + off, gVh + so);
            cp16(base + 24576 + off, gVl + so);
        }
        if (t < 16) cp16(base + 32768 + t * 16, maskb + kt2 * 64 + t * 4);
        asm volatile("cp.async.commit_group;");
    };

    // Stage Q (h+l) into smem [0, 16384)
#pragma unroll
    for (int i = 0; i < 8; i++) {
        int idx = i * 128 + t;
        int arr = idx >> 9, id = idx & 511;
        int r = id >> 3, c = id & 7;
        const __nv_bfloat16* src = (arr ? gQl : gQh) + (size_t)(qt * 64 + r) * HD_ + c * 8;
        cp16(sb + arr * 8192 + off128(r, c), src);
    }
    asm volatile("cp.async.commit_group;");
    load_tile(0, 0);
    asm volatile("cp.async.wait_group 1;" ::: "memory");
    __syncthreads();

    // Q A-fragments, resident for the whole loop
    uint32_t qh[4][4], ql[4][4];
#pragma unroll
    for (int kc = 0; kc < 4; kc++) {
        int r = qbase + (lane & 15), c = 2 * kc + (lane >> 4);
        ldsm4(qh[kc], sb + off128(r, c));
        ldsm4(ql[kc], sb + 8192 + off128(r, c));
    }

    float m0 = NEG_BIG, m1 = NEG_BIG, l0 = 0.f, l1 = 0.f;
    float o[8][4];
#pragma unroll
    for (int j = 0; j < 8; j++)
#pragma unroll
        for (int e = 0; e < 4; e++) o[j][e] = 0.f;

    for (int kt = 0; kt < 16; kt++) {
        if (kt < 15) {
            load_tile(kt + 1, (kt + 1) & 1);
            asm volatile("cp.async.wait_group 1;" ::: "memory");
        } else {
            asm volatile("cp.async.wait_group 0;" ::: "memory");
        }
        __syncthreads();
        const uint32_t base = sb + ATT_BUF0 + (kt & 1) * ATT_BSTR;
        const float* mk = (const float*)(adyn + ATT_BUF0 + (kt & 1) * ATT_BSTR + 32768);

        // ---- S = Q K^T (3-term split) ----
        float sc[8][4];
#pragma unroll
        for (int j = 0; j < 8; j++)
#pragma unroll
            for (int e = 0; e < 4; e++) sc[j][e] = 0.f;

        const int krow = ((lane >> 4) << 3) + (lane & 7);
#pragma unroll
        for (int kc = 0; kc < 4; kc++) {
            const int kchk = 2 * kc + ((lane >> 3) & 1);
#pragma unroll
            for (int nb = 0; nb < 4; nb++) {
                uint32_t off = off128(nb * 16 + krow, kchk);
                uint32_t kh4[4], kl4[4];
                ldsm4(kh4, base + off);
                ldsm4(kl4, base + 8192 + off);
#pragma unroll
                for (int sub = 0; sub < 2; sub++) {
                    int j = 2 * nb + sub;
                    mma16816(sc[j], qh[kc], kh4[2 * sub], kh4[2 * sub + 1]);
                    mma16816(sc[j], ql[kc], kh4[2 * sub], kh4[2 * sub + 1]);
                    mma16816(sc[j], qh[kc], kl4[2 * sub], kl4[2 * sub + 1]);
                }
            }
        }

        // ---- online softmax (rows g, g+8; reduce over 4-lane tig group) ----
        float mt0 = NEG_BIG, mt1 = NEG_BIG;
#pragma unroll
        for (int j = 0; j < 8; j++) {
            float mk0 = mk[8 * j + 2 * tig], mk1 = mk[8 * j + 2 * tig + 1];
            sc[j][0] = sc[j][0] * 0.125f + mk0;
            sc[j][1] = sc[j][1] * 0.125f + mk1;
            sc[j][2] = sc[j][2] * 0.125f + mk0;
            sc[j][3] = sc[j][3] * 0.125f + mk1;
            mt0 = fmaxf(mt0, fmaxf(sc[j][0], sc[j][1]));
            mt1 = fmaxf(mt1, fmaxf(sc[j][2], sc[j][3]));
        }
        mt0 = fmaxf(mt0, __shfl_xor_sync(0xffffffffu, mt0, 1));
        mt0 = fmaxf(mt0, __shfl_xor_sync(0xffffffffu, mt0, 2));
        mt1 = fmaxf(mt1, __shfl_xor_sync(0xffffffffu, mt1, 1));
        mt1 = fmaxf(mt1, __shfl_xor_sync(0xffffffffu, mt1, 2));

        float mn0 = fmaxf(m0, mt0), mn1 = fmaxf(m1, mt1);
        float a0 = __expf(m0 - mn0), a1 = __expf(m1 - mn1);
        m0 = mn0; m1 = mn1;

        float ls0 = 0.f, ls1 = 0.f;
#pragma unroll
        for (int j = 0; j < 8; j++) {
            sc[j][0] = __expf(sc[j][0] - mn0);
            sc[j][1] = __expf(sc[j][1] - mn0);
            sc[j][2] = __expf(sc[j][2] - mn1);
            sc[j][3] = __expf(sc[j][3] - mn1);
            ls0 += sc[j][0] + sc[j][1];
            ls1 += sc[j][2] + sc[j][3];
        }
        ls0 += __shfl_xor_sync(0xffffffffu, ls0, 1);
        ls0 += __shfl_xor_sync(0xffffffffu, ls0, 2);
        ls1 += __shfl_xor_sync(0xffffffffu, ls1, 1);
        ls1 += __shfl_xor_sync(0xffffffffu, ls1, 2);
        l0 = l0 * a0 + ls0;
        l1 = l1 * a1 + ls1;

#pragma unroll
        for (int j = 0; j < 8; j++) {
            o[j][0] *= a0; o[j][1] *= a0;
            o[j][2] *= a1; o[j][3] *= a1;
        }

        // ---- O += P V (P split in-register; V via ldmatrix.trans) ----
#pragma unroll
        for (int kc = 0; kc < 4; kc++) {
            uint32_t pah[4], pal[4];
#pragma unroll
            for (int q = 0; q < 4; q++) {
                int j = 2 * kc + (q >> 1), e = (q & 1) * 2;
                float p0 = sc[j][e], p1 = sc[j][e + 1];
                __nv_bfloat162 hh, llp;
                hh.x  = __float2bfloat16_rn(p0);
                hh.y  = __float2bfloat16_rn(p1);
                llp.x = __float2bfloat16_rn(p0 - __bfloat162float(hh.x));
                llp.y = __float2bfloat16_rn(p1 - __bfloat162float(hh.y));
                pah[q] = *(uint32_t*)&hh;
                pal[q] = *(uint32_t*)&llp;
            }
            const int vrow = 16 * kc + ((lane >> 3) & 1) * 8 + (lane & 7);
            const int vch0 = (lane >> 4);
#pragma unroll
            for (int ng = 0; ng < 4; ng++) {
                uint32_t off = off128(vrow, 2 * ng + vch0);
                uint32_t vh4[4], vl4[4];
                ldsm4t(vh4, base + 16384 + off);
                ldsm4t(vl4, base + 24576 + off);
#pragma unroll
                for (int sub = 0; sub < 2; sub++) {
                    int nb2 = 2 * ng + sub;
                    mma16816(o[nb2], pah, vh4[2 * sub], vh4[2 * sub + 1]);
                    mma16816(o[nb2], pal, vh4[2 * sub], vh4[2 * sub + 1]);
                    mma16816(o[nb2], pah, vl4[2 * sub], vl4[2 * sub + 1]);
                }
            }
        }
        __syncthreads();  // compute done before next iter's prefetch overwrites
    }

    // ---- normalize + write out[b, s, h*64 + col] ----
    float inv0 = 1.f / l0, inv1 = 1.f / l1;
    float* ob = out + ((size_t)b * S_ + qt * 64 + qbase + g) * D_ + h * HD_;
#pragma unroll
    for (int nb2 = 0; nb2 < 8; nb2++) {
        int col = 8 * nb2 + 2 * tig;
        *(float2*)(ob + col)          = make_float2(o[nb2][0] * inv0, o[nb2][1] * inv0);
        *(float2*)(ob + 8 * D_ + col) = make_float2(o[nb2][2] * inv1, o[nb2][3] * inv1);
    }
}

// ---------------------------------------------------------------------------
// Launch
// ---------------------------------------------------------------------------
extern "C" void kernel_launch(void* const* d_in, const int* in_sizes, int n_in,
                              void* d_out, int out_size) {
    (void)in_sizes; (void)n_in; (void)out_size;
    const float* Hs   = (const float*)d_in[0];
    const float* mask = (const float*)d_in[1];
    const float* cosp = (const float*)d_in[2];
    const float* sinp = (const float*)d_in[3];
    const int*   am   = (const int*)d_in[4];
    const float* W    = (const float*)d_in[5];
    const float* bias = (const float*)d_in[6];
    const float* lA   = (const float*)d_in[7];
    const float* lB   = (const float*)d_in[8];
    float* out = (float*)d_out;

    cudaFuncSetAttribute(qkv_mma_kernel, cudaFuncAttributeMaxDynamicSharedMemorySize, QKV_SMEM);
    cudaFuncSetAttribute(attn_mma_kernel, cudaFuncAttributeMaxDynamicSharedMemorySize, ATT_SMEM);

    splitA_kernel<<<(ROWS_ * D_) / 256, 256>>>(Hs);
    splitB_kernel<<<(OD_ * D_) / 256, 256>>>(W);
    lo_kernel<<<ROWS_, 128>>>(Hs, lA, am);
    qkv_mma_kernel<<<dim3(OD_ / 128, ROWS_ / 128), 256, QKV_SMEM>>>(bias, lB, am, cosp, sinp);
    attn_mma_kernel<<<dim3(S_ / 64, B_ * H_), 128, ATT_SMEM>>>(mask, out);
}

// round 12
// speedup vs baseline: 3.4287x; 1.0205x over previous
#include <cuda_runtime.h>
#include <cuda_bf16.h>
#include <cstdint>
#include <cstddef>

// Problem constants
#define B_   8
#define S_   1024
#define D_   1024
#define H_   16
#define HD_  64
#define OD_  3072
#define ROWS_ (B_ * S_)             // 8192
#define BHSZ_ (B_ * H_ * S_ * HD_) // 8,388,608

#define NEG_BIG (-3.0e38f)

// Scratch (device globals, no allocation)
__device__ float g_lo[ROWS_ * 4];
__device__ __nv_bfloat16 g_Ah[ROWS_ * D_];
__device__ __nv_bfloat16 g_Al[ROWS_ * D_];
__device__ __nv_bfloat16 g_Bh[OD_ * D_];
__device__ __nv_bfloat16 g_Bl[OD_ * D_];
// Q/K/V in bf16 split (hi,lo) pairs, layout [b*H+h][s][d]
__device__ __nv_bfloat16 g_Qh[BHSZ_], g_Ql[BHSZ_];
__device__ __nv_bfloat16 g_Kh[BHSZ_], g_Kl[BHSZ_];
__device__ __nv_bfloat16 g_Vh[BHSZ_], g_Vl[BHSZ_];

// ---------------------------------------------------------------------------
// Helpers (sm_80-level features only: cp.async, ldmatrix, mma.sync)
// ---------------------------------------------------------------------------
__device__ __forceinline__ uint32_t smem_u32(const void* p) {
    return (uint32_t)__cvta_generic_to_shared(p);
}
__device__ __forceinline__ void cp16(uint32_t dst, const void* src) {
    asm volatile("cp.async.cg.shared.global [%0], [%1], 16;" :: "r"(dst), "l"(src));
}
__device__ __forceinline__ void ldsm4(uint32_t* r, uint32_t addr) {
    asm volatile("ldmatrix.sync.aligned.m8n8.x4.shared.b16 {%0,%1,%2,%3}, [%4];"
                 : "=r"(r[0]), "=r"(r[1]), "=r"(r[2]), "=r"(r[3]) : "r"(addr));
}
__device__ __forceinline__ void ldsm4t(uint32_t* r, uint32_t addr) {
    asm volatile("ldmatrix.sync.aligned.m8n8.x4.trans.shared.b16 {%0,%1,%2,%3}, [%4];"
                 : "=r"(r[0]), "=r"(r[1]), "=r"(r[2]), "=r"(r[3]) : "r"(addr));
}
__device__ __forceinline__ void mma16816(float* c, const uint32_t* a,
                                         uint32_t b0, uint32_t b1) {
    asm volatile(
        "mma.sync.aligned.m16n8k16.row.col.f32.bf16.bf16.f32 "
        "{%0,%1,%2,%3}, {%4,%5,%6,%7}, {%8,%9}, {%0,%1,%2,%3};"
        : "+f"(c[0]), "+f"(c[1]), "+f"(c[2]), "+f"(c[3])
        : "r"(a[0]), "r"(a[1]), "r"(a[2]), "r"(a[3]), "r"(b0), "r"(b1));
}
__device__ __forceinline__ float dot4(float4 a, float4 b) {
    return a.x * b.x + a.y * b.y + a.z * b.z + a.w * b.w;
}
// Swizzled byte offset of 16B chunk (r, cc) in a tile with 64B rows (qkv GEMM).
__device__ __forceinline__ uint32_t swz(int r, int cc) {
    return (uint32_t)(r * 64 + ((cc ^ ((r >> 1) & 3)) << 4));
}
// Swizzled byte offset of 16B chunk (r, c in [0,8)) in a tile with 128B rows.
__device__ __forceinline__ uint32_t off128(int r, int c) {
    return (uint32_t)(r * 128 + (((c ^ r) & 7) << 4));
}
// Store fp32 pair as bf16 (hi,lo) split pairs.
__device__ __forceinline__ void store_hl(__nv_bfloat16* dh, __nv_bfloat16* dl,
                                         size_t off, float2 v) {
    __nv_bfloat162 h, l;
    h.x = __float2bfloat16_rn(v.x); h.y = __float2bfloat16_rn(v.y);
    l.x = __float2bfloat16_rn(v.x - __bfloat162float(h.x));
    l.y = __float2bfloat16_rn(v.y - __bfloat162float(h.y));
    *(__nv_bfloat162*)(dh + off) = h;
    *(__nv_bfloat162*)(dl + off) = l;
}

// ---------------------------------------------------------------------------
// splitB: W = hi + lo (each bf16)
// ---------------------------------------------------------------------------
__global__ __launch_bounds__(256) void splitB_kernel(const float* __restrict__ src) {
    int i = blockIdx.x * 256 + threadIdx.x;
    float x = src[i];
    __nv_bfloat16 h = __float2bfloat16_rn(x);
    g_Bh[i] = h;
    g_Bl[i] = __float2bfloat16_rn(x - __bfloat162float(h));
}

// ---------------------------------------------------------------------------
// Kernel 1 (fused): per row — LoRA lo projection AND bf16 split of hidden.
// One block per (b,s) row, 128 threads. Hs read once.
// ---------------------------------------------------------------------------
__global__ __launch_bounds__(128) void lo_split_kernel(const float* __restrict__ Hs,
                                                       const float* __restrict__ lA,
                                                       const int*   __restrict__ am) {
    const int row = blockIdx.x;
    const int b   = row >> 10;
    const int a   = am[b];
    const float* hr = Hs + (size_t)row * D_;
    const float* A  = lA + (size_t)a * 4 * D_;

    float p0 = 0.f, p1 = 0.f, p2 = 0.f, p3 = 0.f;
    for (int d = threadIdx.x; d < D_; d += 128) {
        float hv = hr[d];
        __nv_bfloat16 h = __float2bfloat16_rn(hv);
        g_Ah[(size_t)row * D_ + d] = h;
        g_Al[(size_t)row * D_ + d] = __float2bfloat16_rn(hv - __bfloat162float(h));
        p0 += hv * A[d];
        p1 += hv * A[D_ + d];
        p2 += hv * A[2 * D_ + d];
        p3 += hv * A[3 * D_ + d];
    }
    __shared__ float red[4][128];
    red[0][threadIdx.x] = p0;
    red[1][threadIdx.x] = p1;
    red[2][threadIdx.x] = p2;
    red[3][threadIdx.x] = p3;
    __syncthreads();
    for (int off = 64; off > 0; off >>= 1) {
        if (threadIdx.x < off) {
            red[0][threadIdx.x] += red[0][threadIdx.x + off];
            red[1][threadIdx.x] += red[1][threadIdx.x + off];
            red[2][threadIdx.x] += red[2][threadIdx.x + off];
            red[3][threadIdx.x] += red[3][threadIdx.x + off];
        }
        __syncthreads();
    }
    if (threadIdx.x < 4)
        g_lo[row * 4 + threadIdx.x] = red[threadIdx.x][0];
}

// ---------------------------------------------------------------------------
// Kernel 2: QKV GEMM via warp-level mma.sync (bf16 split: ah*bh+al*bh+ah*bl).
// CTA 128x128, BK=32, 256 threads = 8 warps (4M x 2N), warp tile 32x64.
// 3-stage cp.async pipeline; ONE __syncthreads per K-chunk (doubles as
// data-visibility + buffer-recycle barrier); load kk+2 overlaps compute kk.
// Epilogue: bias + LoRA + RoPE, writes Q/K/V as bf16 (hi,lo) split pairs.
// ---------------------------------------------------------------------------
#define TILEB 8192
#define BUFB  (4 * TILEB)
#define QKV_SMEM (3 * BUFB)  // 98304

__global__ __launch_bounds__(256) void qkv_mma_kernel(
    const float* __restrict__ bias, const float* __restrict__ lB,
    const int* __restrict__ am,
    const float* __restrict__ cosp, const float* __restrict__ sinp) {

    extern __shared__ __align__(1024) char dyn[];
    const uint32_t sbase = smem_u32(dyn);

    __shared__ float  s_bias[128];
    __shared__ float4 s_lB[128];

    const int t    = threadIdx.x;
    const int lane = t & 31, wid = t >> 5;
    const int wM = wid >> 1, wN = wid & 1;
    const int rowBase = blockIdx.y * 128;
    const int colBase = blockIdx.x * 128;

    const __nv_bfloat16* gAh = g_Ah + (size_t)rowBase * D_;
    const __nv_bfloat16* gAl = g_Al + (size_t)rowBase * D_;
    const __nv_bfloat16* gBh = g_Bh + (size_t)colBase * D_;
    const __nv_bfloat16* gBl = g_Bl + (size_t)colBase * D_;

    auto load_chunk = [&](int kk, int bi) {
        uint32_t base = sbase + bi * BUFB;
        int gcolb = kk * 32;
#pragma unroll
        for (int rep = 0; rep < 2; rep++) {
            int idx = rep * 256 + t;
            int r = idx >> 2, cc = idx & 3;
            uint32_t off = swz(r, cc);
            size_t go = (size_t)r * D_ + gcolb + cc * 8;
            cp16(base + off,             gAh + go);
            cp16(base + TILEB + off,     gAl + go);
            cp16(base + 2 * TILEB + off, gBh + go);
            cp16(base + 3 * TILEB + off, gBl + go);
        }
        asm volatile("cp.async.commit_group;");
    };

    float acc[2][8][4];
#pragma unroll
    for (int mi = 0; mi < 2; mi++)
#pragma unroll
        for (int nj = 0; nj < 8; nj++)
#pragma unroll
            for (int e = 0; e < 4; e++) acc[mi][nj][e] = 0.f;

    load_chunk(0, 0);
    load_chunk(1, 1);

    int cur = 0, nxt2 = 2;
    for (int kk = 0; kk < 32; kk++) {
        if (kk < 31)
            asm volatile("cp.async.wait_group 1;" ::: "memory");
        else
            asm volatile("cp.async.wait_group 0;" ::: "memory");
        __syncthreads();  // chunk kk visible AND all warps done with chunk kk-1

        if (kk < 30) load_chunk(kk + 2, nxt2);  // overwrites buffer of kk-1

        const uint32_t base = sbase + cur * BUFB;
#pragma unroll
        for (int ks = 0; ks < 2; ks++) {
            uint32_t ah[2][4], al[2][4];
            const int arow = wM * 32 + (lane & 15);
            const int acc_c = ks * 2 + (lane >> 4);
#pragma unroll
            for (int mi = 0; mi < 2; mi++) {
                uint32_t off = swz(arow + mi * 16, acc_c);
                ldsm4(ah[mi], base + off);
                ldsm4(al[mi], base + TILEB + off);
            }
            const int nrow0 = wN * 64 + ((lane >> 4) << 3) + (lane & 7);
            const int bcc   = ks * 2 + ((lane >> 3) & 1);
#pragma unroll
            for (int p = 0; p < 4; p++) {
                uint32_t off = swz(nrow0 + p * 16, bcc);
                uint32_t bh4[4], bl4[4];
                ldsm4(bh4, base + 2 * TILEB + off);
                ldsm4(bl4, base + 3 * TILEB + off);
#pragma unroll
                for (int sub = 0; sub < 2; sub++) {
                    const int nj = 2 * p + sub;
#pragma unroll
                    for (int mi = 0; mi < 2; mi++) {
                        mma16816(acc[mi][nj], ah[mi], bh4[2 * sub], bh4[2 * sub + 1]);
                        mma16816(acc[mi][nj], al[mi], bh4[2 * sub], bh4[2 * sub + 1]);
                        mma16816(acc[mi][nj], ah[mi], bl4[2 * sub], bl4[2 * sub + 1]);
                    }
                }
            }
        }
        cur  = (cur  == 2) ? 0 : cur + 1;
        nxt2 = (nxt2 == 2) ? 0 : nxt2 + 1;
    }

    // ---------------- Epilogue ----------------
    const int b    = rowBase >> 10;
    const int a    = am[b];
    const int part = colBase >> 10;                  // 0=Q, 1=K, 2=V
    const int h    = ((colBase + wN * 64) & 1023) >> 6;

    __nv_bfloat16* dh = (part == 0) ? g_Qh : (part == 1) ? g_Kh : g_Vh;
    __nv_bfloat16* dl = (part == 0) ? g_Ql : (part == 1) ? g_Kl : g_Vl;

    if (t < 128) {
        int o = colBase + t;
        s_bias[t] = bias[o];
        s_lB[t]   = *(const float4*)(lB + ((size_t)a * OD_ + o) * 4);
    }
    __syncthreads();

    const int g   = lane >> 2;
    const int tig = lane & 3;

#pragma unroll
    for (int mi = 0; mi < 2; mi++) {
#pragma unroll
        for (int hh = 0; hh < 2; hh++) {
            const int row = rowBase + wM * 32 + mi * 16 + hh * 8 + g;
            const int s   = row & 1023;
            const float4 lov = *(const float4*)(g_lo + row * 4);
            const size_t rowoff = ((size_t)(b * H_ + h) * S_ + s) * HD_;

            if (part < 2) {
                const float* cr = cosp + (size_t)row * HD_;
                const float* sr = sinp + (size_t)row * HD_;
#pragma unroll
                for (int nj = 0; nj < 4; nj++) {
                    const int c  = nj * 8 + tig * 2;
                    const int cl = wN * 64 + c;
                    float v0 = acc[mi][nj][hh * 2 + 0]     + s_bias[cl]      + 0.25f * dot4(lov, s_lB[cl]);
                    float v1 = acc[mi][nj][hh * 2 + 1]     + s_bias[cl + 1]  + 0.25f * dot4(lov, s_lB[cl + 1]);
                    float u0 = acc[mi][nj + 4][hh * 2 + 0] + s_bias[cl + 32] + 0.25f * dot4(lov, s_lB[cl + 32]);
                    float u1 = acc[mi][nj + 4][hh * 2 + 1] + s_bias[cl + 33] + 0.25f * dot4(lov, s_lB[cl + 33]);
                    float2 clo = *(const float2*)(cr + c),      slo = *(const float2*)(sr + c);
                    float2 chi = *(const float2*)(cr + c + 32), shi = *(const float2*)(sr + c + 32);
                    store_hl(dh, dl, rowoff + c,
                             make_float2(v0 * clo.x - u0 * slo.x, v1 * clo.y - u1 * slo.y));
                    store_hl(dh, dl, rowoff + c + 32,
                             make_float2(u0 * chi.x + v0 * shi.x, u1 * chi.y + v1 * shi.y));
                }
            } else {
#pragma unroll
                for (int nj = 0; nj < 8; nj++) {
                    const int c  = nj * 8 + tig * 2;
                    const int cl = wN * 64 + c;
                    float v0 = acc[mi][nj][hh * 2 + 0] + s_bias[cl]     + 0.25f * dot4(lov, s_lB[cl]);
                    float v1 = acc[mi][nj][hh * 2 + 1] + s_bias[cl + 1] + 0.25f * dot4(lov, s_lB[cl + 1]);
                    store_hl(dh, dl, rowoff + c, make_float2(v0, v1));
                }
            }
        }
    }
}

// ---------------------------------------------------------------------------
// Kernel 3: flash attention via mma.sync (bf16 splits everywhere).
// CTA = 64 queries x (b,h); 128 threads = 4 warps x 16 query rows.
// smem 82432B -> 2 CTAs/SM (cross-CTA overlap hides per-tile syncs).
// ---------------------------------------------------------------------------
#define ATT_BUF0 16384
#define ATT_BSTR 33024
#define ATT_SMEM (ATT_BUF0 + 2 * ATT_BSTR)  // 82432

__global__ __launch_bounds__(128) void attn_mma_kernel(const float* __restrict__ mask,
                                                       float* __restrict__ out) {
    extern __shared__ __align__(1024) char adyn[];
    const uint32_t sb = smem_u32(adyn);
    const int t = threadIdx.x, lane = t & 31, w = t >> 5;
    const int g = lane >> 2, tig = lane & 3;
    const int bh = blockIdx.y, b = bh >> 4, h = bh & 15;
    const int qt = blockIdx.x;
    const int qbase = w * 16;

    const __nv_bfloat16* gQh = g_Qh + (size_t)bh * S_ * HD_;
    const __nv_bfloat16* gQl = g_Ql + (size_t)bh * S_ * HD_;
    const __nv_bfloat16* gKh = g_Kh + (size_t)bh * S_ * HD_;
    const __nv_bfloat16* gKl = g_Kl + (size_t)bh * S_ * HD_;
    const __nv_bfloat16* gVh = g_Vh + (size_t)bh * S_ * HD_;
    const __nv_bfloat16* gVl = g_Vl + (size_t)bh * S_ * HD_;
    const float* maskb = mask + b * S_;

    auto load_tile = [&](int kt2, int bi) {
        uint32_t base = sb + ATT_BUF0 + bi * ATT_BSTR;
#pragma unroll
        for (int i = 0; i < 4; i++) {
            int idx = i * 128 + t;
            int r = idx >> 3, c = idx & 7;
            uint32_t off = off128(r, c);
            size_t so = (size_t)(kt2 * 64 + r) * HD_ + c * 8;
            cp16(base + off,         gKh + so);
            cp16(base + 8192 + off,  gKl + so);
            cp16(base + 16384 + off, gVh + so);
            cp16(base + 24576 + off, gVl + so);
        }
        if (t < 16) cp16(base + 32768 + t * 16, maskb + kt2 * 64 + t * 4);
        asm volatile("cp.async.commit_group;");
    };

    // Stage Q (h+l) into smem [0, 16384)
#pragma unroll
    for (int i = 0; i < 8; i++) {
        int idx = i * 128 + t;
        int arr = idx >> 9, id = idx & 511;
        int r = id >> 3, c = id & 7;
        const __nv_bfloat16* src = (arr ? gQl : gQh) + (size_t)(qt * 64 + r) * HD_ + c * 8;
        cp16(sb + arr * 8192 + off128(r, c), src);
    }
    asm volatile("cp.async.commit_group;");
    load_tile(0, 0);
    asm volatile("cp.async.wait_group 1;" ::: "memory");
    __syncthreads();

    // Q A-fragments, resident for the whole loop
    uint32_t qh[4][4], ql[4][4];
#pragma unroll
    for (int kc = 0; kc < 4; kc++) {
        int r = qbase + (lane & 15), c = 2 * kc + (lane >> 4);
        ldsm4(qh[kc], sb + off128(r, c));
        ldsm4(ql[kc], sb + 8192 + off128(r, c));
    }

    float m0 = NEG_BIG, m1 = NEG_BIG, l0 = 0.f, l1 = 0.f;
    float o[8][4];
#pragma unroll
    for (int j = 0; j < 8; j++)
#pragma unroll
        for (int e = 0; e < 4; e++) o[j][e] = 0.f;

    for (int kt = 0; kt < 16; kt++) {
        if (kt < 15) {
            load_tile(kt + 1, (kt + 1) & 1);
            asm volatile("cp.async.wait_group 1;" ::: "memory");
        } else {
            asm volatile("cp.async.wait_group 0;" ::: "memory");
        }
        __syncthreads();
        const uint32_t base = sb + ATT_BUF0 + (kt & 1) * ATT_BSTR;
        const float* mk = (const float*)(adyn + ATT_BUF0 + (kt & 1) * ATT_BSTR + 32768);

        // ---- S = Q K^T (3-term split) ----
        float sc[8][4];
#pragma unroll
        for (int j = 0; j < 8; j++)
#pragma unroll
            for (int e = 0; e < 4; e++) sc[j][e] = 0.f;

        const int krow = ((lane >> 4) << 3) + (lane & 7);
#pragma unroll
        for (int kc = 0; kc < 4; kc++) {
            const int kchk = 2 * kc + ((lane >> 3) & 1);
#pragma unroll
            for (int nb = 0; nb < 4; nb++) {
                uint32_t off = off128(nb * 16 + krow, kchk);
                uint32_t kh4[4], kl4[4];
                ldsm4(kh4, base + off);
                ldsm4(kl4, base + 8192 + off);
#pragma unroll
                for (int sub = 0; sub < 2; sub++) {
                    int j = 2 * nb + sub;
                    mma16816(sc[j], qh[kc], kh4[2 * sub], kh4[2 * sub + 1]);
                    mma16816(sc[j], ql[kc], kh4[2 * sub], kh4[2 * sub + 1]);
                    mma16816(sc[j], qh[kc], kl4[2 * sub], kl4[2 * sub + 1]);
                }
            }
        }

        // ---- online softmax (rows g, g+8; reduce over 4-lane tig group) ----
        float mt0 = NEG_BIG, mt1 = NEG_BIG;
#pragma unroll
        for (int j = 0; j < 8; j++) {
            float mk0 = mk[8 * j + 2 * tig], mk1 = mk[8 * j + 2 * tig + 1];
            sc[j][0] = sc[j][0] * 0.125f + mk0;
            sc[j][1] = sc[j][1] * 0.125f + mk1;
            sc[j][2] = sc[j][2] * 0.125f + mk0;
            sc[j][3] = sc[j][3] * 0.125f + mk1;
            mt0 = fmaxf(mt0, fmaxf(sc[j][0], sc[j][1]));
            mt1 = fmaxf(mt1, fmaxf(sc[j][2], sc[j][3]));
        }
        mt0 = fmaxf(mt0, __shfl_xor_sync(0xffffffffu, mt0, 1));
        mt0 = fmaxf(mt0, __shfl_xor_sync(0xffffffffu, mt0, 2));
        mt1 = fmaxf(mt1, __shfl_xor_sync(0xffffffffu, mt1, 1));
        mt1 = fmaxf(mt1, __shfl_xor_sync(0xffffffffu, mt1, 2));

        float mn0 = fmaxf(m0, mt0), mn1 = fmaxf(m1, mt1);
        float a0 = __expf(m0 - mn0), a1 = __expf(m1 - mn1);
        m0 = mn0; m1 = mn1;

        float ls0 = 0.f, ls1 = 0.f;
#pragma unroll
        for (int j = 0; j < 8; j++) {
            sc[j][0] = __expf(sc[j][0] - mn0);
            sc[j][1] = __expf(sc[j][1] - mn0);
            sc[j][2] = __expf(sc[j][2] - mn1);
            sc[j][3] = __expf(sc[j][3] - mn1);
            ls0 += sc[j][0] + sc[j][1];
            ls1 += sc[j][2] + sc[j][3];
        }
        ls0 += __shfl_xor_sync(0xffffffffu, ls0, 1);
        ls0 += __shfl_xor_sync(0xffffffffu, ls0, 2);
        ls1 += __shfl_xor_sync(0xffffffffu, ls1, 1);
        ls1 += __shfl_xor_sync(0xffffffffu, ls1, 2);
        l0 = l0 * a0 + ls0;
        l1 = l1 * a1 + ls1;

#pragma unroll
        for (int j = 0; j < 8; j++) {
            o[j][0] *= a0; o[j][1] *= a0;
            o[j][2] *= a1; o[j][3] *= a1;
        }

        // ---- O += P V (P split in-register; V via ldmatrix.trans) ----
#pragma unroll
        for (int kc = 0; kc < 4; kc++) {
            uint32_t pah[4], pal[4];
#pragma unroll
            for (int q = 0; q < 4; q++) {
                int j = 2 * kc + (q >> 1), e = (q & 1) * 2;
                float p0 = sc[j][e], p1 = sc[j][e + 1];
                __nv_bfloat162 hh, llp;
                hh.x  = __float2bfloat16_rn(p0);
                hh.y  = __float2bfloat16_rn(p1);
                llp.x = __float2bfloat16_rn(p0 - __bfloat162float(hh.x));
                llp.y = __float2bfloat16_rn(p1 - __bfloat162float(hh.y));
                pah[q] = *(uint32_t*)&hh;
                pal[q] = *(uint32_t*)&llp;
            }
            const int vrow = 16 * kc + ((lane >> 3) & 1) * 8 + (lane & 7);
            const int vch0 = (lane >> 4);
#pragma unroll
            for (int ng = 0; ng < 4; ng++) {
                uint32_t off = off128(vrow, 2 * ng + vch0);
                uint32_t vh4[4], vl4[4];
                ldsm4t(vh4, base + 16384 + off);
                ldsm4t(vl4, base + 24576 + off);
#pragma unroll
                for (int sub = 0; sub < 2; sub++) {
                    int nb2 = 2 * ng + sub;
                    mma16816(o[nb2], pah, vh4[2 * sub], vh4[2 * sub + 1]);
                    mma16816(o[nb2], pal, vh4[2 * sub], vh4[2 * sub + 1]);
                    mma16816(o[nb2], pah, vl4[2 * sub], vl4[2 * sub + 1]);
                }
            }
        }
        __syncthreads();  // compute done before next iter's prefetch overwrites
    }

    // ---- normalize + write out[b, s, h*64 + col] ----
    float inv0 = 1.f / l0, inv1 = 1.f / l1;
    float* ob = out + ((size_t)b * S_ + qt * 64 + qbase + g) * D_ + h * HD_;
#pragma unroll
    for (int nb2 = 0; nb2 < 8; nb2++) {
        int col = 8 * nb2 + 2 * tig;
        *(float2*)(ob + col)          = make_float2(o[nb2][0] * inv0, o[nb2][1] * inv0);
        *(float2*)(ob + 8 * D_ + col) = make_float2(o[nb2][2] * inv1, o[nb2][3] * inv1);
    }
}

// ---------------------------------------------------------------------------
// Launch
// ---------------------------------------------------------------------------
extern "C" void kernel_launch(void* const* d_in, const int* in_sizes, int n_in,
                              void* d_out, int out_size) {
    (void)in_sizes; (void)n_in; (void)out_size;
    const float* Hs   = (const float*)d_in[0];
    const float* mask = (const float*)d_in[1];
    const float* cosp = (const float*)d_in[2];
    const float* sinp = (const float*)d_in[3];
    const int*   am   = (const int*)d_in[4];
    const float* W    = (const float*)d_in[5];
    const float* bias = (const float*)d_in[6];
    const float* lA   = (const float*)d_in[7];
    const float* lB   = (const float*)d_in[8];
    float* out = (float*)d_out;

    cudaFuncSetAttribute(qkv_mma_kernel, cudaFuncAttributeMaxDynamicSharedMemorySize, QKV_SMEM);
    cudaFuncSetAttribute(attn_mma_kernel, cudaFuncAttributeMaxDynamicSharedMemorySize, ATT_SMEM);

    splitB_kernel<<<(OD_ * D_) / 256, 256>>>(W);
    lo_split_kernel<<<ROWS_, 128>>>(Hs, lA, am);
    qkv_mma_kernel<<<dim3(OD_ / 128, ROWS_ / 128), 256, QKV_SMEM>>>(bias, lB, am, cosp, sinp);
    attn_mma_kernel<<<dim3(S_ / 64, B_ * H_), 128, ATT_SMEM>>>(mask, out);
}

// round 15
// speedup vs baseline: 3.8863x; 1.1335x over previous
#include <cuda_runtime.h>
#include <cuda_bf16.h>
#include <cstdint>
#include <cstddef>

// Problem constants
#define B_   8
#define S_   1024
#define D_   1024
#define H_   16
#define HD_  64
#define OD_  3072
#define ROWS_ (B_ * S_)             // 8192
#define BHSZ_ (B_ * H_ * S_ * HD_) // 8,388,608

#define NEG_BIG (-3.0e38f)

// Scratch (device globals, no allocation)
__device__ float g_lo[ROWS_ * 4];
__device__ __nv_bfloat16 g_Ah[ROWS_ * D_];
__device__ __nv_bfloat16 g_Al[ROWS_ * D_];
__device__ __nv_bfloat16 g_Bh[OD_ * D_];
__device__ __nv_bfloat16 g_Bl[OD_ * D_];
// Q/K/V in bf16 split (hi,lo) pairs, layout [b*H+h][s][d]
__device__ __nv_bfloat16 g_Qh[BHSZ_], g_Ql[BHSZ_];
__device__ __nv_bfloat16 g_Kh[BHSZ_], g_Kl[BHSZ_];
__device__ __nv_bfloat16 g_Vh[BHSZ_], g_Vl[BHSZ_];

// ---------------------------------------------------------------------------
// Helpers (sm_80-level features only: cp.async, ldmatrix, mma.sync)
// ---------------------------------------------------------------------------
__device__ __forceinline__ uint32_t smem_u32(const void* p) {
    return (uint32_t)__cvta_generic_to_shared(p);
}
__device__ __forceinline__ void cp16(uint32_t dst, const void* src) {
    asm volatile("cp.async.cg.shared.global [%0], [%1], 16;" :: "r"(dst), "l"(src));
}
__device__ __forceinline__ void ldsm4(uint32_t* r, uint32_t addr) {
    asm volatile("ldmatrix.sync.aligned.m8n8.x4.shared.b16 {%0,%1,%2,%3}, [%4];"
                 : "=r"(r[0]), "=r"(r[1]), "=r"(r[2]), "=r"(r[3]) : "r"(addr));
}
__device__ __forceinline__ void ldsm4t(uint32_t* r, uint32_t addr) {
    asm volatile("ldmatrix.sync.aligned.m8n8.x4.trans.shared.b16 {%0,%1,%2,%3}, [%4];"
                 : "=r"(r[0]), "=r"(r[1]), "=r"(r[2]), "=r"(r[3]) : "r"(addr));
}
__device__ __forceinline__ void mma16816(float* c, const uint32_t* a,
                                         uint32_t b0, uint32_t b1) {
    asm volatile(
        "mma.sync.aligned.m16n8k16.row.col.f32.bf16.bf16.f32 "
        "{%0,%1,%2,%3}, {%4,%5,%6,%7}, {%8,%9}, {%0,%1,%2,%3};"
        : "+f"(c[0]), "+f"(c[1]), "+f"(c[2]), "+f"(c[3])
        : "r"(a[0]), "r"(a[1]), "r"(a[2]), "r"(a[3]), "r"(b0), "r"(b1));
}
__device__ __forceinline__ float dot4(float4 a, float4 b) {
    return a.x * b.x + a.y * b.y + a.z * b.z + a.w * b.w;
}
// Swizzled byte offset of 16B chunk (r, cc) in a tile with 64B rows (qkv GEMM).
__device__ __forceinline__ uint32_t swz(int r, int cc) {
    return (uint32_t)(r * 64 + ((cc ^ ((r >> 1) & 3)) << 4));
}
// Swizzled byte offset of 16B chunk (r, c in [0,8)) in a tile with 128B rows.
__device__ __forceinline__ uint32_t off128(int r, int c) {
    return (uint32_t)(r * 128 + (((c ^ r) & 7) << 4));
}
// Store fp32 pair as bf16 (hi,lo) split pairs.
__device__ __forceinline__ void store_hl(__nv_bfloat16* dh, __nv_bfloat16* dl,
                                         size_t off, float2 v) {
    __nv_bfloat162 h, l;
    h.x = __float2bfloat16_rn(v.x); h.y = __float2bfloat16_rn(v.y);
    l.x = __float2bfloat16_rn(v.x - __bfloat162float(h.x));
    l.y = __float2bfloat16_rn(v.y - __bfloat162float(h.y));
    *(__nv_bfloat162*)(dh + off) = h;
    *(__nv_bfloat162*)(dl + off) = l;
}

// ---------------------------------------------------------------------------
// splitB: W = hi + lo (each bf16)
// ---------------------------------------------------------------------------
__global__ __launch_bounds__(256) void splitB_kernel(const float* __restrict__ src) {
    int i = blockIdx.x * 256 + threadIdx.x;
    float x = src[i];
    __nv_bfloat16 h = __float2bfloat16_rn(x);
    g_Bh[i] = h;
    g_Bl[i] = __float2bfloat16_rn(x - __bfloat162float(h));
}

// ---------------------------------------------------------------------------
// Kernel 1 (fused): per row — LoRA lo projection AND bf16 split of hidden.
// ---------------------------------------------------------------------------
__global__ __launch_bounds__(128) void lo_split_kernel(const float* __restrict__ Hs,
                                                       const float* __restrict__ lA,
                                                       const int*   __restrict__ am) {
    const int row = blockIdx.x;
    const int b   = row >> 10;
    const int a   = am[b];
    const float* hr = Hs + (size_t)row * D_;
    const float* A  = lA + (size_t)a * 4 * D_;

    float p0 = 0.f, p1 = 0.f, p2 = 0.f, p3 = 0.f;
    for (int d = threadIdx.x; d < D_; d += 128) {
        float hv = hr[d];
        __nv_bfloat16 h = __float2bfloat16_rn(hv);
        g_Ah[(size_t)row * D_ + d] = h;
        g_Al[(size_t)row * D_ + d] = __float2bfloat16_rn(hv - __bfloat162float(h));
        p0 += hv * A[d];
        p1 += hv * A[D_ + d];
        p2 += hv * A[2 * D_ + d];
        p3 += hv * A[3 * D_ + d];
    }
    __shared__ float red[4][128];
    red[0][threadIdx.x] = p0;
    red[1][threadIdx.x] = p1;
    red[2][threadIdx.x] = p2;
    red[3][threadIdx.x] = p3;
    __syncthreads();
    for (int off = 64; off > 0; off >>= 1) {
        if (threadIdx.x < off) {
            red[0][threadIdx.x] += red[0][threadIdx.x + off];
            red[1][threadIdx.x] += red[1][threadIdx.x + off];
            red[2][threadIdx.x] += red[2][threadIdx.x + off];
            red[3][threadIdx.x] += red[3][threadIdx.x + off];
        }
        __syncthreads();
    }
    if (threadIdx.x < 4)
        g_lo[row * 4 + threadIdx.x] = red[threadIdx.x][0];
}

// ---------------------------------------------------------------------------
// Kernel 2: QKV GEMM via warp-level mma.sync (bf16 split: ah*bh+al*bh+ah*bl).
// CTA 128x128, BK=32, 256 threads = 8 warps (4M x 2N), warp tile 32x64.
// 3-stage cp.async pipeline, one __syncthreads per K-chunk.
// __launch_bounds__(256, 2): cap regs at 128 -> 2 CTAs/SM for cross-overlap.
// ---------------------------------------------------------------------------
#define TILEB 8192
#define BUFB  (4 * TILEB)
#define QKV_SMEM (3 * BUFB)  // 98304

__global__ __launch_bounds__(256, 2) void qkv_mma_kernel(
    const float* __restrict__ bias, const float* __restrict__ lB,
    const int* __restrict__ am,
    const float* __restrict__ cosp, const float* __restrict__ sinp) {

    extern __shared__ __align__(1024) char dyn[];
    const uint32_t sbase = smem_u32(dyn);

    __shared__ float  s_bias[128];
    __shared__ float4 s_lB[128];

    const int t    = threadIdx.x;
    const int lane = t & 31, wid = t >> 5;
    const int wM = wid >> 1, wN = wid & 1;
    const int rowBase = blockIdx.y * 128;
    const int colBase = blockIdx.x * 128;

    const __nv_bfloat16* gAh = g_Ah + (size_t)rowBase * D_;
    const __nv_bfloat16* gAl = g_Al + (size_t)rowBase * D_;
    const __nv_bfloat16* gBh = g_Bh + (size_t)colBase * D_;
    const __nv_bfloat16* gBl = g_Bl + (size_t)colBase * D_;

    auto load_chunk = [&](int kk, int bi) {
        uint32_t base = sbase + bi * BUFB;
        int gcolb = kk * 32;
#pragma unroll
        for (int rep = 0; rep < 2; rep++) {
            int idx = rep * 256 + t;
            int r = idx >> 2, cc = idx & 3;
            uint32_t off = swz(r, cc);
            size_t go = (size_t)r * D_ + gcolb + cc * 8;
            cp16(base + off,             gAh + go);
            cp16(base + TILEB + off,     gAl + go);
            cp16(base + 2 * TILEB + off, gBh + go);
            cp16(base + 3 * TILEB + off, gBl + go);
        }
        asm volatile("cp.async.commit_group;");
    };

    float acc[2][8][4];
#pragma unroll
    for (int mi = 0; mi < 2; mi++)
#pragma unroll
        for (int nj = 0; nj < 8; nj++)
#pragma unroll
            for (int e = 0; e < 4; e++) acc[mi][nj][e] = 0.f;

    load_chunk(0, 0);
    load_chunk(1, 1);

    int cur = 0, nxt2 = 2;
    for (int kk = 0; kk < 32; kk++) {
        if (kk < 31)
            asm volatile("cp.async.wait_group 1;" ::: "memory");
        else
            asm volatile("cp.async.wait_group 0;" ::: "memory");
        __syncthreads();  // chunk kk visible AND all warps done with chunk kk-1

        if (kk < 30) load_chunk(kk + 2, nxt2);  // overwrites buffer of kk-1

        const uint32_t base = sbase + cur * BUFB;
#pragma unroll
        for (int ks = 0; ks < 2; ks++) {
            uint32_t ah[2][4], al[2][4];
            const int arow = wM * 32 + (lane & 15);
            const int acc_c = ks * 2 + (lane >> 4);
#pragma unroll
            for (int mi = 0; mi < 2; mi++) {
                uint32_t off = swz(arow + mi * 16, acc_c);
                ldsm4(ah[mi], base + off);
                ldsm4(al[mi], base + TILEB + off);
            }
            const int nrow0 = wN * 64 + ((lane >> 4) << 3) + (lane & 7);
            const int bcc   = ks * 2 + ((lane >> 3) & 1);
#pragma unroll
            for (int p = 0; p < 4; p++) {
                uint32_t off = swz(nrow0 + p * 16, bcc);
                uint32_t bh4[4], bl4[4];
                ldsm4(bh4, base + 2 * TILEB + off);
                ldsm4(bl4, base + 3 * TILEB + off);
#pragma unroll
                for (int sub = 0; sub < 2; sub++) {
                    const int nj = 2 * p + sub;
#pragma unroll
                    for (int mi = 0; mi < 2; mi++) {
                        mma16816(acc[mi][nj], ah[mi], bh4[2 * sub], bh4[2 * sub + 1]);
                        mma16816(acc[mi][nj], al[mi], bh4[2 * sub], bh4[2 * sub + 1]);
                        mma16816(acc[mi][nj], ah[mi], bl4[2 * sub], bl4[2 * sub + 1]);
                    }
                }
            }
        }
        cur  = (cur  == 2) ? 0 : cur + 1;
        nxt2 = (nxt2 == 2) ? 0 : nxt2 + 1;
    }

    // ---------------- Epilogue ----------------
    const int b    = rowBase >> 10;
    const int a    = am[b];
    const int part = colBase >> 10;                  // 0=Q, 1=K, 2=V
    const int h    = ((colBase + wN * 64) & 1023) >> 6;

    __nv_bfloat16* dh = (part == 0) ? g_Qh : (part == 1) ? g_Kh : g_Vh;
    __nv_bfloat16* dl = (part == 0) ? g_Ql : (part == 1) ? g_Kl : g_Vl;

    if (t < 128) {
        int o = colBase + t;
        s_bias[t] = bias[o];
        s_lB[t]   = *(const float4*)(lB + ((size_t)a * OD_ + o) * 4);
    }
    __syncthreads();

    const int g   = lane >> 2;
    const int tig = lane & 3;

#pragma unroll
    for (int mi = 0; mi < 2; mi++) {
#pragma unroll
        for (int hh = 0; hh < 2; hh++) {
            const int row = rowBase + wM * 32 + mi * 16 + hh * 8 + g;
            const int s   = row & 1023;
            const float4 lov = *(const float4*)(g_lo + row * 4);
            const size_t rowoff = ((size_t)(b * H_ + h) * S_ + s) * HD_;

            if (part < 2) {
                const float* cr = cosp + (size_t)row * HD_;
                const float* sr = sinp + (size_t)row * HD_;
#pragma unroll
                for (int nj = 0; nj < 4; nj++) {
                    const int c  = nj * 8 + tig * 2;
                    const int cl = wN * 64 + c;
                    float v0 = acc[mi][nj][hh * 2 + 0]     + s_bias[cl]      + 0.25f * dot4(lov, s_lB[cl]);
                    float v1 = acc[mi][nj][hh * 2 + 1]     + s_bias[cl + 1]  + 0.25f * dot4(lov, s_lB[cl + 1]);
                    float u0 = acc[mi][nj + 4][hh * 2 + 0] + s_bias[cl + 32] + 0.25f * dot4(lov, s_lB[cl + 32]);
                    float u1 = acc[mi][nj + 4][hh * 2 + 1] + s_bias[cl + 33] + 0.25f * dot4(lov, s_lB[cl + 33]);
                    float2 clo = *(const float2*)(cr + c),      slo = *(const float2*)(sr + c);
                    float2 chi = *(const float2*)(cr + c + 32), shi = *(const float2*)(sr + c + 32);
                    store_hl(dh, dl, rowoff + c,
                             make_float2(v0 * clo.x - u0 * slo.x, v1 * clo.y - u1 * slo.y));
                    store_hl(dh, dl, rowoff + c + 32,
                             make_float2(u0 * chi.x + v0 * shi.x, u1 * chi.y + v1 * shi.y));
                }
            } else {
#pragma unroll
                for (int nj = 0; nj < 8; nj++) {
                    const int c  = nj * 8 + tig * 2;
                    const int cl = wN * 64 + c;
                    float v0 = acc[mi][nj][hh * 2 + 0] + s_bias[cl]     + 0.25f * dot4(lov, s_lB[cl]);
                    float v1 = acc[mi][nj][hh * 2 + 1] + s_bias[cl + 1] + 0.25f * dot4(lov, s_lB[cl + 1]);
                    store_hl(dh, dl, rowoff + c, make_float2(v0, v1));
                }
            }
        }
    }
}

// ---------------------------------------------------------------------------
// Kernel 3: flash attention via mma.sync (bf16 splits everywhere).
// CTA = 64 queries x (b,h); 128 threads = 4 warps x 16 query rows.
// Q A-fragments loaded DIRECTLY from global (no Q smem stage):
// smem = 2 x 33024 = 66048B -> 3 CTAs/SM.
// ---------------------------------------------------------------------------
#define ATT_BSTR 33024
#define ATT_SMEM (2 * ATT_BSTR)  // 66048

__global__ __launch_bounds__(128) void attn_mma_kernel(const float* __restrict__ mask,
                                                       float* __restrict__ out) {
    extern __shared__ __align__(1024) char adyn[];
    const uint32_t sb = smem_u32(adyn);
    const int t = threadIdx.x, lane = t & 31, w = t >> 5;
    const int g = lane >> 2, tig = lane & 3;
    const int bh = blockIdx.y, b = bh >> 4, h = bh & 15;
    const int qt = blockIdx.x;
    const int qbase = w * 16;

    const __nv_bfloat16* gQh = g_Qh + (size_t)bh * S_ * HD_;
    const __nv_bfloat16* gQl = g_Ql + (size_t)bh * S_ * HD_;
    const __nv_bfloat16* gKh = g_Kh + (size_t)bh * S_ * HD_;
    const __nv_bfloat16* gKl = g_Kl + (size_t)bh * S_ * HD_;
    const __nv_bfloat16* gVh = g_Vh + (size_t)bh * S_ * HD_;
    const __nv_bfloat16* gVl = g_Vl + (size_t)bh * S_ * HD_;
    const float* maskb = mask + b * S_;

    auto load_tile = [&](int kt2, int bi) {
        uint32_t base = sb + bi * ATT_BSTR;
#pragma unroll
        for (int i = 0; i < 4; i++) {
            int idx = i * 128 + t;
            int r = idx >> 3, c = idx & 7;
            uint32_t off = off128(r, c);
            size_t so = (size_t)(kt2 * 64 + r) * HD_ + c * 8;
            cp16(base + off,         gKh + so);
            cp16(base + 8192 + off,  gKl + so);
            cp16(base + 16384 + off, gVh + so);
            cp16(base + 24576 + off, gVl + so);
        }
        if (t < 16) cp16(base + 32768 + t * 16, maskb + kt2 * 64 + t * 4);
        asm volatile("cp.async.commit_group;");
    };

    load_tile(0, 0);

    // Q A-fragments loaded directly from global (m16n8k16 A layout):
    // a0=(g, 2tig), a1=(g+8, 2tig), a2=(g, 2tig+8), a3=(g+8, 2tig+8) per 16-col chunk.
    uint32_t qh[4][4], ql[4][4];
    {
        const size_t r0 = (size_t)(qt * 64 + qbase + g) * HD_;
        const size_t r1 = (size_t)(qt * 64 + qbase + g + 8) * HD_;
#pragma unroll
        for (int kc = 0; kc < 4; kc++) {
            const int c = 16 * kc + 2 * tig;
            qh[kc][0] = *(const uint32_t*)(gQh + r0 + c);
            qh[kc][1] = *(const uint32_t*)(gQh + r1 + c);
            qh[kc][2] = *(const uint32_t*)(gQh + r0 + c + 8);
            qh[kc][3] = *(const uint32_t*)(gQh + r1 + c + 8);
            ql[kc][0] = *(const uint32_t*)(gQl + r0 + c);
            ql[kc][1] = *(const uint32_t*)(gQl + r1 + c);
            ql[kc][2] = *(const uint32_t*)(gQl + r0 + c + 8);
            ql[kc][3] = *(const uint32_t*)(gQl + r1 + c + 8);
        }
    }

    float m0 = NEG_BIG, m1 = NEG_BIG, l0 = 0.f, l1 = 0.f;
    float o[8][4];
#pragma unroll
    for (int j = 0; j < 8; j++)
#pragma unroll
        for (int e = 0; e < 4; e++) o[j][e] = 0.f;

    for (int kt = 0; kt < 16; kt++) {
        if (kt < 15) {
            load_tile(kt + 1, (kt + 1) & 1);
            asm volatile("cp.async.wait_group 1;" ::: "memory");
        } else {
            asm volatile("cp.async.wait_group 0;" ::: "memory");
        }
        __syncthreads();
        const uint32_t base = sb + (kt & 1) * ATT_BSTR;
        const float* mk = (const float*)(adyn + (kt & 1) * ATT_BSTR + 32768);

        // ---- S = Q K^T (3-term split) ----
        float sc[8][4];
#pragma unroll
        for (int j = 0; j < 8; j++)
#pragma unroll
            for (int e = 0; e < 4; e++) sc[j][e] = 0.f;

        const int krow = ((lane >> 4) << 3) + (lane & 7);
#pragma unroll
        for (int kc = 0; kc < 4; kc++) {
            const int kchk = 2 * kc + ((lane >> 3) & 1);
#pragma unroll
            for (int nb = 0; nb < 4; nb++) {
                uint32_t off = off128(nb * 16 + krow, kchk);
                uint32_t kh4[4], kl4[4];
                ldsm4(kh4, base + off);
                ldsm4(kl4, base + 8192 + off);
#pragma unroll
                for (int sub = 0; sub < 2; sub++) {
                    int j = 2 * nb + sub;
                    mma16816(sc[j], qh[kc], kh4[2 * sub], kh4[2 * sub + 1]);
                    mma16816(sc[j], ql[kc], kh4[2 * sub], kh4[2 * sub + 1]);
                    mma16816(sc[j], qh[kc], kl4[2 * sub], kl4[2 * sub + 1]);
                }
            }
        }

        // ---- online softmax (rows g, g+8; reduce over 4-lane tig group) ----
        float mt0 = NEG_BIG, mt1 = NEG_BIG;
#pragma unroll
        for (int j = 0; j < 8; j++) {
            float mk0 = mk[8 * j + 2 * tig], mk1 = mk[8 * j + 2 * tig + 1];
            sc[j][0] = sc[j][0] * 0.125f + mk0;
            sc[j][1] = sc[j][1] * 0.125f + mk1;
            sc[j][2] = sc[j][2] * 0.125f + mk0;
            sc[j][3] = sc[j][3] * 0.125f + mk1;
            mt0 = fmaxf(mt0, fmaxf(sc[j][0], sc[j][1]));
            mt1 = fmaxf(mt1, fmaxf(sc[j][2], sc[j][3]));
        }
        mt0 = fmaxf(mt0, __shfl_xor_sync(0xffffffffu, mt0, 1));
        mt0 = fmaxf(mt0, __shfl_xor_sync(0xffffffffu, mt0, 2));
        mt1 = fmaxf(mt1, __shfl_xor_sync(0xffffffffu, mt1, 1));
        mt1 = fmaxf(mt1, __shfl_xor_sync(0xffffffffu, mt1, 2));

        float mn0 = fmaxf(m0, mt0), mn1 = fmaxf(m1, mt1);
        float a0 = __expf(m0 - mn0), a1 = __expf(m1 - mn1);
        m0 = mn0; m1 = mn1;

        float ls0 = 0.f, ls1 = 0.f;
#pragma unroll
        for (int j = 0; j < 8; j++) {
            sc[j][0] = __expf(sc[j][0] - mn0);
            sc[j][1] = __expf(sc[j][1] - mn0);
            sc[j][2] = __expf(sc[j][2] - mn1);
            sc[j][3] = __expf(sc[j][3] - mn1);
            ls0 += sc[j][0] + sc[j][1];
            ls1 += sc[j][2] + sc[j][3];
        }
        ls0 += __shfl_xor_sync(0xffffffffu, ls0, 1);
        ls0 += __shfl_xor_sync(0xffffffffu, ls0, 2);
        ls1 += __shfl_xor_sync(0xffffffffu, ls1, 1);
        ls1 += __shfl_xor_sync(0xffffffffu, ls1, 2);
        l0 = l0 * a0 + ls0;
        l1 = l1 * a1 + ls1;

#pragma unroll
        for (int j = 0; j < 8; j++) {
            o[j][0] *= a0; o[j][1] *= a0;
            o[j][2] *= a1; o[j][3] *= a1;
        }

        // ---- O += P V (P split in-register; V via ldmatrix.trans) ----
#pragma unroll
        for (int kc = 0; kc < 4; kc++) {
            uint32_t pah[4], pal[4];
#pragma unroll
            for (int q = 0; q < 4; q++) {
                int j = 2 * kc + (q >> 1), e = (q & 1) * 2;
                float p0 = sc[j][e], p1 = sc[j][e + 1];
                __nv_bfloat162 hh, llp;
                hh.x  = __float2bfloat16_rn(p0);
                hh.y  = __float2bfloat16_rn(p1);
                llp.x = __float2bfloat16_rn(p0 - __bfloat162float(hh.x));
                llp.y = __float2bfloat16_rn(p1 - __bfloat162float(hh.y));
                pah[q] = *(uint32_t*)&hh;
                pal[q] = *(uint32_t*)&llp;
            }
            const int vrow = 16 * kc + ((lane >> 3) & 1) * 8 + (lane & 7);
            const int vch0 = (lane >> 4);
#pragma unroll
            for (int ng = 0; ng < 4; ng++) {
                uint32_t off = off128(vrow, 2 * ng + vch0);
                uint32_t vh4[4], vl4[4];
                ldsm4t(vh4, base + 16384 + off);
                ldsm4t(vl4, base + 24576 + off);
#pragma unroll
                for (int sub = 0; sub < 2; sub++) {
                    int nb2 = 2 * ng + sub;
                    mma16816(o[nb2], pah, vh4[2 * sub], vh4[2 * sub + 1]);
                    mma16816(o[nb2], pal, vh4[2 * sub], vh4[2 * sub + 1]);
                    mma16816(o[nb2], pah, vl4[2 * sub], vl4[2 * sub + 1]);
                }
            }
        }
        __syncthreads();  // compute done before next iter's prefetch overwrites
    }

    // ---- normalize + write out[b, s, h*64 + col] ----
    float inv0 = 1.f / l0, inv1 = 1.f / l1;
    float* ob = out + ((size_t)b * S_ + qt * 64 + qbase + g) * D_ + h * HD_;
#pragma unroll
    for (int nb2 = 0; nb2 < 8; nb2++) {
        int col = 8 * nb2 + 2 * tig;
        *(float2*)(ob + col)          = make_float2(o[nb2][0] * inv0, o[nb2][1] * inv0);
        *(float2*)(ob + 8 * D_ + col) = make_float2(o[nb2][2] * inv1, o[nb2][3] * inv1);
    }
}

// ---------------------------------------------------------------------------
// Launch
// ---------------------------------------------------------------------------
extern "C" void kernel_launch(void* const* d_in, const int* in_sizes, int n_in,
                              void* d_out, int out_size) {
    (void)in_sizes; (void)n_in; (void)out_size;
    const float* Hs   = (const float*)d_in[0];
    const float* mask = (const float*)d_in[1];
    const float* cosp = (const float*)d_in[2];
    const float* sinp = (const float*)d_in[3];
    const int*   am   = (const int*)d_in[4];
    const float* W    = (const float*)d_in[5];
    const float* bias = (const float*)d_in[6];
    const float* lA   = (const float*)d_in[7];
    const float* lB   = (const float*)d_in[8];
    float* out = (float*)d_out;

    cudaFuncSetAttribute(qkv_mma_kernel, cudaFuncAttributeMaxDynamicSharedMemorySize, QKV_SMEM);
    cudaFuncSetAttribute(attn_mma_kernel, cudaFuncAttributeMaxDynamicSharedMemorySize, ATT_SMEM);

    splitB_kernel<<<(OD_ * D_) / 256, 256>>>(W);
    lo_split_kernel<<<ROWS_, 128>>>(Hs, lA, am);
    qkv_mma_kernel<<<dim3(OD_ / 128, ROWS_ / 128), 256, QKV_SMEM>>>(bias, lB, am, cosp, sinp);
    attn_mma_kernel<<<dim3(S_ / 64, B_ * H_), 128, ATT_SMEM>>>(mask, out);
}